// round 7
// baseline (speedup 1.0000x reference)
#include <cuda_runtime.h>
#include <math.h>

#define NG   8
#define ND   16
#define NL   1024
#define NB   16
#define NE   8
#define NOUT 64
#define NKS  3
#define NK   4
#define NLP  1022
#define TILE 128
#define NTILES 8
#define KK   48            // conv1 GEMM K-dim = ND*NKS
#define XTP  136           // xt row stride  (136%32=8 -> conflict-free frags)
#define W1P  72            // w1t row stride (72%32=8)
#define WETP 72            // W_eff row stride
#define HSP  136           // h row stride

typedef unsigned long long u64;
typedef unsigned int u32;

// Scratch (static device global — no allocation)
__device__ float g_gates[NG*NB*NE];

__device__ __forceinline__ float tanh_fast(float x) {
    float r;
    asm("tanh.approx.f32 %0, %1;" : "=f"(r) : "f"(x));
    return r;
}
__device__ __forceinline__ float round_tf32(float x) {
    u32 r;
    asm("cvt.rna.tf32.f32 %0, %1;" : "=r"(r) : "f"(x));
    return __uint_as_float(r);
}
// tf32 mma: D(16x8) = A(16x8) @ B(8x8) + D
__device__ __forceinline__ void mma_tf32(float& c0, float& c1, float& c2, float& c3,
                                         u32 a0, u32 a1, u32 a2, u32 a3,
                                         u32 b0, u32 b1) {
    asm("mma.sync.aligned.m16n8k8.row.col.f32.tf32.tf32.f32 "
        "{%0,%1,%2,%3}, {%4,%5,%6,%7}, {%8,%9}, {%0,%1,%2,%3};"
        : "+f"(c0), "+f"(c1), "+f"(c2), "+f"(c3)
        : "r"(a0), "r"(a1), "r"(a2), "r"(a3), "r"(b0), "r"(b1));
}

__device__ __forceinline__ float cv_sq(const float* v) {
    float m = 0.f;
    #pragma unroll
    for (int i = 0; i < NE; i++) m += v[i];
    m *= (1.f / NE);
    float var = 0.f;
    #pragma unroll
    for (int i = 0; i < NE; i++) { float d = v[i] - m; var += d * d; }
    var *= (1.f / (NE - 1));
    return var / (m * m + 1e-10f);
}

// ---------------------------------------------------------------------------
// loss kernel (trailing)
// ---------------------------------------------------------------------------
__global__ void loss_kernel(float* __restrict__ out) {
    const int t = threadIdx.x;
    __shared__ float s_imp[NG][NE];
    __shared__ float s_ld[NG][NE];
    __shared__ float lsum[NG];
    if (t < NG * NE) {
        const int g = t >> 3, e = t & 7;
        float imp = 0.f, ld = 0.f;
        #pragma unroll
        for (int bb = 0; bb < NB; bb++) {
            float v = g_gates[((g * NB + bb) * NE) + e];
            imp += v;
            ld  += (v > 0.f) ? 1.f : 0.f;
        }
        s_imp[g][e] = imp;
        s_ld[g][e]  = ld;
    }
    __syncthreads();
    if (t < NG) lsum[t] = cv_sq(s_imp[t]) + cv_sq(s_ld[t]);
    __syncthreads();
    if (t == 0) {
        float total = 0.f;
        #pragma unroll
        for (int i = 0; i < NG; i++) total += lsum[i];
        out[(size_t)NB * NG * NOUT * NLP] = 0.01f * total;
    }
}

// ---------------------------------------------------------------------------
// Main kernel: gates (warp 0) + W_eff fold + conv1(tf32 mma)+tanh + GEMM(tf32 mma)
// grid (NTILES, NB, NG), 256 threads.
// ---------------------------------------------------------------------------
__global__ __launch_bounds__(256)
void main_kernel(const float* __restrict__ x,
                 const float* __restrict__ w_gate,
                 const float* __restrict__ w1,
                 const float* __restrict__ b1,
                 const float* __restrict__ w2,
                 const float* __restrict__ b2,
                 float* __restrict__ out) {
    const int tile = blockIdx.x;
    const int b    = blockIdx.y;
    const int g    = blockIdx.z;
    const int l0g  = tile * TILE;
    const int tlen = min(TILE, NLP - l0g);

    extern __shared__ float smem[];
    float* xt  = smem;                         // [kk][l]  48*136 = 6528 (tf32)
    float* w1t = xt  + KK * XTP;               // [kk][o]  48*72  = 3456 (tf32)
    float* wet = w1t + KK * W1P;               // [k][o]   64*72  = 4608 (tf32)
    float* hs  = wet + NOUT * WETP;            // [k][l]   64*136 = 8704 (tf32)
    float* bes = hs  + NOUT * HSP;             // 64
    float* b1s = bes + NOUT;                   // 64
    float* gsm = b1s + NOUT;                   // 8 gates

    const int t = threadIdx.x;
    const int c = t & 31;          // lane
    const int r = t >> 5;          // warp id
    const int gid = c >> 2;        // 0..7  (mma fragment group)
    const int tg  = c & 3;         // 0..3

    // ---- warp 0: compute gates for (g,b) ----
    if (r == 0) {
        float plog[NE];
        #pragma unroll
        for (int e = 0; e < NE; e++) plog[e] = 0.f;
        #pragma unroll
        for (int i = c; i < ND * 5; i += 32) {
            int d = i / 5, j = i % 5;
            float xv = x[(size_t)b * (NG * ND * NL) + (size_t)(g * ND + d) * NL + (NL - 6 + j)];
            const float4* w4 = (const float4*)(w_gate + ((size_t)g * ND * 5 + i) * NE);
            float4 wa = w4[0], wb = w4[1];
            plog[0] += xv * wa.x; plog[1] += xv * wa.y;
            plog[2] += xv * wa.z; plog[3] += xv * wa.w;
            plog[4] += xv * wb.x; plog[5] += xv * wb.y;
            plog[6] += xv * wb.z; plog[7] += xv * wb.w;
        }
        #pragma unroll
        for (int off = 16; off >= 1; off >>= 1)
            #pragma unroll
            for (int e = 0; e < NE; e++)
                plog[e] += __shfl_xor_sync(0xffffffffu, plog[e], off);

        if (c == 0) {
            float m = plog[0];
            #pragma unroll
            for (int e = 1; e < NE; e++) m = fmaxf(m, plog[e]);
            float p[NE]; float s = 0.f;
            #pragma unroll
            for (int e = 0; e < NE; e++) { p[e] = __expf(plog[e] - m); s += p[e]; }
            float inv = 1.f / s;
            #pragma unroll
            for (int e = 0; e < NE; e++) p[e] *= inv;

            float q[NE];
            #pragma unroll
            for (int e = 0; e < NE; e++) q[e] = p[e];
            float tv[NK]; int ti[NK];
            #pragma unroll
            for (int k = 0; k < NK; k++) {
                float best = -1e30f; int bi = 0;
                #pragma unroll
                for (int e = 0; e < NE; e++)
                    if (q[e] > best) { best = q[e]; bi = e; }
                tv[k] = best; ti[k] = bi; q[bi] = -1e30f;
            }
            float dsum = tv[0] + tv[1] + tv[2] + tv[3] + 1e-6f;
            float gates[NE];
            #pragma unroll
            for (int e = 0; e < NE; e++) gates[e] = 0.f;
            #pragma unroll
            for (int k = 0; k < NK; k++) gates[ti[k]] = tv[k] / dsum;

            #pragma unroll
            for (int e = 0; e < NE; e++) gsm[e] = gates[e];
            if (tile == 0) {
                const size_t combine_sz = (size_t)NB * NG * NOUT * NLP;
                #pragma unroll
                for (int e = 0; e < NE; e++) {
                    g_gates[(g * NB + b) * NE + e] = gates[e];
                    out[combine_sz + 1 + (size_t)(b * NE + e) * NG + g] = gates[e];
                }
            }
        }
    }

    // ---- cooperative loads (all warps) ----
    // xt[kk][l] = tf32( x[g,b][kk/3][l0g + l + kk%3] ), zero-padded at end
    const float* xb0 = x + (size_t)b * (NG * ND * NL) + (size_t)g * ND * NL;
    for (int idx = t; idx < KK * XTP; idx += 256) {
        const int kk = idx / XTP, l = idx % XTP;
        if (l < TILE) {
            const int d = kk / NKS, k = kk % NKS;
            const int gx = l0g + l + k;
            float v = (gx < NL) ? xb0[(size_t)d * NL + gx] : 0.f;
            xt[idx] = round_tf32(v);
        }
    }
    // w1t[kk][o] = tf32( w1[g][o][kk] )   (kk = d*3+k, contiguous in gmem)
    const float* w1g = w1 + (size_t)g * NOUT * KK;
    for (int idx = t; idx < NOUT * KK; idx += 256) {
        const int o = idx / KK, kk = idx % KK;
        w1t[kk * W1P + o] = round_tf32(w1g[idx]);
    }
    if (t < NOUT) b1s[t] = b1[g * NOUT + t];
    __syncthreads();   // gates in gsm, xt/w1t ready

    // ---- W_eff fold (tf32-rounded): wet[k][o] = sum_e g[e]*w2[g][o*E+e][k] ----
    {
        float gv[NE];
        #pragma unroll
        for (int e = 0; e < NE; e++) gv[e] = gsm[e];
        const float* w2g = w2 + (size_t)g * NOUT * NE * NOUT;
        #pragma unroll
        for (int it = 0; it < (NOUT * NOUT) / 256; it++) {
            int idx = t + it * 256;
            int o = idx >> 6, i = idx & 63;
            const float* wrow = w2g + (size_t)o * NE * NOUT + i;
            float acc = 0.f;
            #pragma unroll
            for (int e = 0; e < NE; e++) acc += gv[e] * wrow[e * NOUT];
            wet[i * WETP + o] = round_tf32(acc);
        }
        if (t < NOUT) {
            const float* brow = b2 + (size_t)g * NOUT * NE + t * NE;
            float acc = 0.f;
            #pragma unroll
            for (int e = 0; e < NE; e++) acc += gv[e] * brow[e];
            bes[t] = acc;
        }
    }

    // ---- phase 2: h = tanh(conv1(x)) via tf32 mma (64x128x48) ----
    // warp r -> mt = r&3 (16 o-rows), nh = r>>2 (64 cols)
    {
        const int mt = r & 3;
        const int nh = r >> 2;
        const int orow0 = mt * 16 + gid;

        float cacc[8][4];
        const float bv0 = b1s[orow0];
        const float bv1 = b1s[orow0 + 8];
        #pragma unroll
        for (int nt = 0; nt < 8; nt++) {
            cacc[nt][0] = bv0; cacc[nt][1] = bv0;
            cacc[nt][2] = bv1; cacc[nt][3] = bv1;
        }
        const u32* w1u = (const u32*)w1t;
        const u32* xtu = (const u32*)xt;
        #pragma unroll
        for (int kt = 0; kt < KK / 8; kt++) {
            const int k0 = kt * 8;
            const u32 a0 = w1u[(k0 + tg) * W1P + orow0];
            const u32 a1 = w1u[(k0 + tg) * W1P + orow0 + 8];
            const u32 a2 = w1u[(k0 + tg + 4) * W1P + orow0];
            const u32 a3 = w1u[(k0 + tg + 4) * W1P + orow0 + 8];
            #pragma unroll
            for (int nt = 0; nt < 8; nt++) {
                const int ncol = nh * 64 + nt * 8 + gid;
                const u32 b0 = xtu[(k0 + tg) * XTP + ncol];
                const u32 b1v = xtu[(k0 + tg + 4) * XTP + ncol];
                mma_tf32(cacc[nt][0], cacc[nt][1], cacc[nt][2], cacc[nt][3],
                         a0, a1, a2, a3, b0, b1v);
            }
        }
        // tanh + tf32-round, store into hs in fragment layout
        #pragma unroll
        for (int nt = 0; nt < 8; nt++) {
            const int col0 = nh * 64 + nt * 8 + tg * 2;
            *(float2*)&hs[orow0 * HSP + col0] =
                make_float2(round_tf32(tanh_fast(cacc[nt][0])),
                            round_tf32(tanh_fast(cacc[nt][1])));
            *(float2*)&hs[(orow0 + 8) * HSP + col0] =
                make_float2(round_tf32(tanh_fast(cacc[nt][2])),
                            round_tf32(tanh_fast(cacc[nt][3])));
        }
    }
    __syncthreads();

    // ---- phase 3: out = W_eff @ h + b_eff via tf32 mma (64x128x64) ----
    {
        const int mt = r & 3;
        const int nh = r >> 2;
        const int orow0 = mt * 16 + gid;

        float cacc[8][4];
        const float bv0 = bes[orow0];
        const float bv1 = bes[orow0 + 8];
        #pragma unroll
        for (int nt = 0; nt < 8; nt++) {
            cacc[nt][0] = bv0; cacc[nt][1] = bv0;
            cacc[nt][2] = bv1; cacc[nt][3] = bv1;
        }
        const u32* wetu = (const u32*)wet;
        const u32* hsu  = (const u32*)hs;
        #pragma unroll
        for (int kt = 0; kt < 8; kt++) {
            const int k0 = kt * 8;
            const u32 a0 = wetu[(k0 + tg) * WETP + orow0];
            const u32 a1 = wetu[(k0 + tg) * WETP + orow0 + 8];
            const u32 a2 = wetu[(k0 + tg + 4) * WETP + orow0];
            const u32 a3 = wetu[(k0 + tg + 4) * WETP + orow0 + 8];
            #pragma unroll
            for (int nt = 0; nt < 8; nt++) {
                const int ncol = nh * 64 + nt * 8 + gid;
                const u32 b0 = hsu[(k0 + tg) * HSP + ncol];
                const u32 b1v = hsu[(k0 + tg + 4) * HSP + ncol];
                mma_tf32(cacc[nt][0], cacc[nt][1], cacc[nt][2], cacc[nt][3],
                         a0, a1, a2, a3, b0, b1v);
            }
        }
        // store to gmem
        #pragma unroll
        for (int nt = 0; nt < 8; nt++) {
            const int colt = nh * 64 + nt * 8 + tg * 2;
            float* row0 = out + ((size_t)(b * NG + g) * NOUT + orow0) * NLP + l0g + colt;
            float* row1 = out + ((size_t)(b * NG + g) * NOUT + orow0 + 8) * NLP + l0g + colt;
            if (colt + 1 < tlen) {
                *(float2*)row0 = make_float2(cacc[nt][0], cacc[nt][1]);
                *(float2*)row1 = make_float2(cacc[nt][2], cacc[nt][3]);
            } else if (colt < tlen) {
                row0[0] = cacc[nt][0];
                row1[0] = cacc[nt][2];
            }
        }
    }
}

// ---------------------------------------------------------------------------
extern "C" void kernel_launch(void* const* d_in, const int* in_sizes, int n_in,
                              void* d_out, int out_size) {
    const float* x       = (const float*)d_in[0];
    const float* w_gate  = (const float*)d_in[1];
    const float* conv1_w = (const float*)d_in[2];
    const float* conv1_b = (const float*)d_in[3];
    const float* conv2_w = (const float*)d_in[4];
    const float* conv2_b = (const float*)d_in[5];
    float* out = (float*)d_out;

    const int smem_bytes = (KK * XTP + KK * W1P + NOUT * WETP
                            + NOUT * HSP + 2 * NOUT + NE) * sizeof(float);
    cudaFuncSetAttribute(main_kernel,
                         cudaFuncAttributeMaxDynamicSharedMemorySize, smem_bytes);

    main_kernel<<<dim3(NTILES, NB, NG), 256, smem_bytes>>>(
        x, w_gate, conv1_w, conv1_b, conv2_w, conv2_b, out);
    loss_kernel<<<1, 64>>>(out);
}

// round 8
// speedup vs baseline: 1.3122x; 1.3122x over previous
#include <cuda_runtime.h>
#include <math.h>

#define NG   8
#define ND   16
#define NL   1024
#define NB   16
#define NE   8
#define NOUT 64
#define NKS  3
#define NK   4
#define NLP  1022
#define TILE 128
#define NTILES 8
#define XPAD 132
#define WETP 72            // W_eff smem row stride: 72%32=8 -> conflict-free frags
#define HSP  136           // h smem row stride:    136%32=8

typedef unsigned long long u64;
typedef unsigned int u32;

// Scratch (static device globals — no allocation)
__device__ float g_gates[NG*NB*NE];
__device__ float g_weff[NG*NB*NOUT*NOUT];   // [blk][k][o], tf32-rounded
__device__ float g_beff[NG*NB*NOUT];

__device__ __forceinline__ float tanh_fast(float x) {
    float r;
    asm("tanh.approx.f32 %0, %1;" : "=f"(r) : "f"(x));
    return r;
}
__device__ __forceinline__ float round_tf32(float x) {
    u32 r;
    asm("cvt.rna.tf32.f32 %0, %1;" : "=r"(r) : "f"(x));
    return __uint_as_float(r);
}
__device__ __forceinline__ void ffma2(u64& d, u64 a, u64 b) {
    asm("fma.rn.f32x2 %0, %1, %2, %0;" : "+l"(d) : "l"(a), "l"(b));
}
__device__ __forceinline__ u64 pack_dup(float x) {
    u64 r; asm("mov.b64 %0, {%1, %1};" : "=l"(r) : "f"(x)); return r;
}
__device__ __forceinline__ float2 unpack2(u64 v) {
    float2 f; asm("mov.b64 {%0, %1}, %2;" : "=f"(f.x), "=f"(f.y) : "l"(v)); return f;
}
__device__ __forceinline__ void mma_tf32(float& c0, float& c1, float& c2, float& c3,
                                         u32 a0, u32 a1, u32 a2, u32 a3,
                                         u32 b0, u32 b1) {
    asm("mma.sync.aligned.m16n8k8.row.col.f32.tf32.tf32.f32 "
        "{%0,%1,%2,%3}, {%4,%5,%6,%7}, {%8,%9}, {%0,%1,%2,%3};"
        : "+f"(c0), "+f"(c1), "+f"(c2), "+f"(c3)
        : "r"(a0), "r"(a1), "r"(a2), "r"(a3), "r"(b0), "r"(b1));
}

__device__ __forceinline__ float cv_sq(const float* v) {
    float m = 0.f;
    #pragma unroll
    for (int i = 0; i < NE; i++) m += v[i];
    m *= (1.f / NE);
    float var = 0.f;
    #pragma unroll
    for (int i = 0; i < NE; i++) { float d = v[i] - m; var += d * d; }
    var *= (1.f / (NE - 1));
    return var / (m * m + 1e-10f);
}

// ---------------------------------------------------------------------------
// Kernel A: gates + W_eff fold, one block per (g,b). 256 threads.
// ---------------------------------------------------------------------------
__global__ __launch_bounds__(256)
void prep_kernel(const float* __restrict__ x,
                 const float* __restrict__ w_gate,
                 const float* __restrict__ w2,
                 const float* __restrict__ b2,
                 float* __restrict__ out) {
    const int blk = blockIdx.x;   // g*NB + b
    const int g = blk >> 4;
    const int b = blk & 15;
    const int t = threadIdx.x;
    const int c = t & 31;
    const int r = t >> 5;

    __shared__ float gsm[NE];
    __shared__ float wef_s[NOUT * 65];   // [o][k] padded -> conflict-free transpose

    // ---- warp 0: gates ----
    if (r == 0) {
        float plog[NE];
        #pragma unroll
        for (int e = 0; e < NE; e++) plog[e] = 0.f;
        #pragma unroll
        for (int i = c; i < ND * 5; i += 32) {
            int d = i / 5, j = i % 5;
            float xv = x[(size_t)b * (NG * ND * NL) + (size_t)(g * ND + d) * NL + (NL - 6 + j)];
            const float4* w4 = (const float4*)(w_gate + ((size_t)g * ND * 5 + i) * NE);
            float4 wa = w4[0], wb = w4[1];
            plog[0] += xv * wa.x; plog[1] += xv * wa.y;
            plog[2] += xv * wa.z; plog[3] += xv * wa.w;
            plog[4] += xv * wb.x; plog[5] += xv * wb.y;
            plog[6] += xv * wb.z; plog[7] += xv * wb.w;
        }
        #pragma unroll
        for (int off = 16; off >= 1; off >>= 1)
            #pragma unroll
            for (int e = 0; e < NE; e++)
                plog[e] += __shfl_xor_sync(0xffffffffu, plog[e], off);

        if (c == 0) {
            float m = plog[0];
            #pragma unroll
            for (int e = 1; e < NE; e++) m = fmaxf(m, plog[e]);
            float p[NE]; float s = 0.f;
            #pragma unroll
            for (int e = 0; e < NE; e++) { p[e] = __expf(plog[e] - m); s += p[e]; }
            float inv = 1.f / s;
            #pragma unroll
            for (int e = 0; e < NE; e++) p[e] *= inv;

            float q[NE];
            #pragma unroll
            for (int e = 0; e < NE; e++) q[e] = p[e];
            float tv[NK]; int ti[NK];
            #pragma unroll
            for (int k = 0; k < NK; k++) {
                float best = -1e30f; int bi = 0;
                #pragma unroll
                for (int e = 0; e < NE; e++)
                    if (q[e] > best) { best = q[e]; bi = e; }
                tv[k] = best; ti[k] = bi; q[bi] = -1e30f;
            }
            float dsum = tv[0] + tv[1] + tv[2] + tv[3] + 1e-6f;
            float gates[NE];
            #pragma unroll
            for (int e = 0; e < NE; e++) gates[e] = 0.f;
            #pragma unroll
            for (int k = 0; k < NK; k++) gates[ti[k]] = tv[k] / dsum;

            const size_t combine_sz = (size_t)NB * NG * NOUT * NLP;
            #pragma unroll
            for (int e = 0; e < NE; e++) {
                gsm[e] = gates[e];
                g_gates[blk * NE + e] = gates[e];
                out[combine_sz + 1 + (size_t)(b * NE + e) * NG + g] = gates[e];
            }
        }
    }
    __syncthreads();

    float gv[NE];
    #pragma unroll
    for (int e = 0; e < NE; e++) gv[e] = gsm[e];

    // fold (coalesced reads): wef_s[o][k] = sum_e gv[e] * w2[g][o*E+e][k]
    const float* w2g = w2 + (size_t)g * NOUT * NE * NOUT;
    #pragma unroll
    for (int it = 0; it < (NOUT * NOUT) / 256; it++) {
        int idx = t + it * 256;
        int o = idx >> 6, k = idx & 63;
        const float* wrow = w2g + (size_t)o * NE * NOUT + k;
        float acc = 0.f;
        #pragma unroll
        for (int e = 0; e < NE; e++) acc += gv[e] * wrow[e * NOUT];
        wef_s[o * 65 + k] = round_tf32(acc);
    }
    if (t < NOUT) {
        const float* brow = b2 + (size_t)g * NOUT * NE + t * NE;
        float acc = 0.f;
        #pragma unroll
        for (int e = 0; e < NE; e++) acc += gv[e] * brow[e];
        g_beff[blk * NOUT + t] = acc;
    }
    __syncthreads();

    // transposed coalesced write: g_weff[blk][k][o]
    float* wef = g_weff + (size_t)blk * NOUT * NOUT;
    #pragma unroll
    for (int it = 0; it < (NOUT * NOUT) / 256; it++) {
        int idx = t + it * 256;
        int k = idx >> 6, o = idx & 63;
        wef[idx] = wef_s[o * 65 + k];
    }
}

// ---------------------------------------------------------------------------
// Main kernel: conv1 (FFMA2) + tanh + tf32-MMA GEMM. Loss tail in block (0,0,0).
// grid (NTILES, NB, NG), 256 threads.
// ---------------------------------------------------------------------------
__global__ __launch_bounds__(256)
void main_kernel(const float* __restrict__ x,
                 const float* __restrict__ w1,
                 const float* __restrict__ b1,
                 float* __restrict__ out) {
    const int tile = blockIdx.x;
    const int b    = blockIdx.y;
    const int g    = blockIdx.z;
    const int l0g  = tile * TILE;
    const int tlen = min(TILE, NLP - l0g);

    extern __shared__ float smem[];
    float* xs  = smem;                         // ND * XPAD     = 2112
    float* w1t = xs  + ND * XPAD;              // [d*3+k][o]    = 3072
    float* wet = w1t + ND * NKS * NOUT;        // [k][o] pad 72 = 4608 (tf32)
    float* hs  = wet + NOUT * WETP;            // [k][l] pad136 = 8704 (tf32)
    float* bes = hs  + NOUT * HSP;             // 64
    float* b1s = bes + NOUT;                   // 64

    const int t = threadIdx.x;
    const int c = t & 31;          // lane
    const int r = t >> 5;          // warp id
    const int ob = r * 8;          // phase-2: 8 contiguous output channels
    const int l0 = c * 4;          // phase-2: 4 columns

    // ---- cooperative loads ----
    const float* xb = x + (size_t)b * (NG * ND * NL) + (size_t)g * ND * NL + l0g;
    const int ncols = min(TILE + 2, NL - l0g);
    for (int idx = t; idx < ND * XPAD; idx += 256) {
        int d = idx / XPAD, cc = idx % XPAD;
        xs[idx] = (cc < ncols) ? xb[(size_t)d * NL + cc] : 0.f;
    }
    const float* w1g = w1 + (size_t)g * NOUT * ND * NKS;
    for (int idx = t; idx < NOUT * ND * NKS; idx += 256) {
        int o = idx / (ND * NKS), dk = idx % (ND * NKS);
        w1t[dk * NOUT + o] = w1g[idx];
    }
    // W_eff copy with pad: wet[k*WETP+o] = g_weff[blk][k*64+o]
    const float* weg = g_weff + (size_t)(g * NB + b) * NOUT * NOUT;
    #pragma unroll
    for (int it = 0; it < (NOUT * NOUT) / 256; it++) {
        int idx = t + it * 256;
        wet[(idx >> 6) * WETP + (idx & 63)] = weg[idx];
    }
    if (t < NOUT) {
        bes[t] = g_beff[(g * NB + b) * NOUT + t];
        b1s[t] = b1[g * NOUT + t];
    }
    __syncthreads();

    // ---- phase 2: h = tanh(conv1(x)) in fp32 (FFMA2), tf32-rounded store ----
    {
        u64 acc2[4][4];
        #pragma unroll
        for (int i2 = 0; i2 < 4; i2++) {
            u64 bv = *(const u64*)&b1s[ob + 2 * i2];
            #pragma unroll
            for (int j = 0; j < 4; j++) acc2[i2][j] = bv;
        }
        #pragma unroll
        for (int d = 0; d < ND; d++) {
            const float4 xa = *(const float4*)&xs[d * XPAD + l0];
            const float4 xc = *(const float4*)&xs[d * XPAD + l0 + 4];
            u64 xd[6];
            xd[0] = pack_dup(xa.x); xd[1] = pack_dup(xa.y);
            xd[2] = pack_dup(xa.z); xd[3] = pack_dup(xa.w);
            xd[4] = pack_dup(xc.x); xd[5] = pack_dup(xc.y);
            #pragma unroll
            for (int k = 0; k < NKS; k++) {
                const ulonglong2 wp0 = *(const ulonglong2*)&w1t[(d * NKS + k) * NOUT + ob];
                const ulonglong2 wp1 = *(const ulonglong2*)&w1t[(d * NKS + k) * NOUT + ob + 4];
                const u64 wp[4] = {wp0.x, wp0.y, wp1.x, wp1.y};
                #pragma unroll
                for (int i2 = 0; i2 < 4; i2++) {
                    ffma2(acc2[i2][0], wp[i2], xd[k + 0]);
                    ffma2(acc2[i2][1], wp[i2], xd[k + 1]);
                    ffma2(acc2[i2][2], wp[i2], xd[k + 2]);
                    ffma2(acc2[i2][3], wp[i2], xd[k + 3]);
                }
            }
        }
        #pragma unroll
        for (int i2 = 0; i2 < 4; i2++) {
            float2 v0 = unpack2(acc2[i2][0]);
            float2 v1 = unpack2(acc2[i2][1]);
            float2 v2 = unpack2(acc2[i2][2]);
            float2 v3 = unpack2(acc2[i2][3]);
            *(float4*)&hs[(ob + 2 * i2) * HSP + l0] =
                make_float4(round_tf32(tanh_fast(v0.x)), round_tf32(tanh_fast(v1.x)),
                            round_tf32(tanh_fast(v2.x)), round_tf32(tanh_fast(v3.x)));
            *(float4*)&hs[(ob + 2 * i2 + 1) * HSP + l0] =
                make_float4(round_tf32(tanh_fast(v0.y)), round_tf32(tanh_fast(v1.y)),
                            round_tf32(tanh_fast(v2.y)), round_tf32(tanh_fast(v3.y)));
        }
    }
    __syncthreads();

    // ---- phase 3: out = W_eff @ h + b_eff via tf32 mma (m16n8k8) ----
    {
        const int mt = r & 3;
        const int nh = r >> 2;
        const int gid = c >> 2;
        const int tg  = c & 3;
        const int orow0 = mt * 16 + gid;

        float cacc[8][4];
        const float bv0 = bes[orow0];
        const float bv1 = bes[orow0 + 8];
        #pragma unroll
        for (int nt = 0; nt < 8; nt++) {
            cacc[nt][0] = bv0; cacc[nt][1] = bv0;
            cacc[nt][2] = bv1; cacc[nt][3] = bv1;
        }
        const u32* wetu = (const u32*)wet;
        const u32* hsu  = (const u32*)hs;
        #pragma unroll
        for (int kt = 0; kt < 8; kt++) {
            const int k0 = kt * 8;
            const u32 a0 = wetu[(k0 + tg) * WETP + orow0];
            const u32 a1 = wetu[(k0 + tg) * WETP + orow0 + 8];
            const u32 a2 = wetu[(k0 + tg + 4) * WETP + orow0];
            const u32 a3 = wetu[(k0 + tg + 4) * WETP + orow0 + 8];
            #pragma unroll
            for (int nt = 0; nt < 8; nt++) {
                const int ncol = nh * 64 + nt * 8 + gid;
                const u32 b0 = hsu[(k0 + tg) * HSP + ncol];
                const u32 b1v = hsu[(k0 + tg + 4) * HSP + ncol];
                mma_tf32(cacc[nt][0], cacc[nt][1], cacc[nt][2], cacc[nt][3],
                         a0, a1, a2, a3, b0, b1v);
            }
        }
        #pragma unroll
        for (int nt = 0; nt < 8; nt++) {
            const int colt = nh * 64 + nt * 8 + tg * 2;
            float* row0 = out + ((size_t)(b * NG + g) * NOUT + orow0) * NLP + l0g + colt;
            float* row1 = out + ((size_t)(b * NG + g) * NOUT + orow0 + 8) * NLP + l0g + colt;
            if (colt + 1 < tlen) {
                *(float2*)row0 = make_float2(cacc[nt][0], cacc[nt][1]);
                *(float2*)row1 = make_float2(cacc[nt][2], cacc[nt][3]);
            } else if (colt < tlen) {
                row0[0] = cacc[nt][0];
                row1[0] = cacc[nt][2];
            }
        }
    }

    // ---- loss tail: block (0,0,0) only; g_gates visible from prep_kernel ----
    if (tile == 0 && b == 0 && g == 0) {
        __syncthreads();
        float* s_imp = smem;              // reuse smem: [NG][NE]
        float* s_ld  = smem + NG * NE;
        float* lsum  = smem + 2 * NG * NE;
        if (t < NG * NE) {
            const int gg = t >> 3, e = t & 7;
            float imp = 0.f, ld = 0.f;
            #pragma unroll
            for (int bb = 0; bb < NB; bb++) {
                float v = g_gates[((gg * NB + bb) * NE) + e];
                imp += v;
                ld  += (v > 0.f) ? 1.f : 0.f;
            }
            s_imp[gg * NE + e] = imp;
            s_ld[gg * NE + e]  = ld;
        }
        __syncthreads();
        if (t < NG) lsum[t] = cv_sq(&s_imp[t * NE]) + cv_sq(&s_ld[t * NE]);
        __syncthreads();
        if (t == 0) {
            float total = 0.f;
            #pragma unroll
            for (int i = 0; i < NG; i++) total += lsum[i];
            out[(size_t)NB * NG * NOUT * NLP] = 0.01f * total;
        }
    }
}

// ---------------------------------------------------------------------------
extern "C" void kernel_launch(void* const* d_in, const int* in_sizes, int n_in,
                              void* d_out, int out_size) {
    const float* x       = (const float*)d_in[0];
    const float* w_gate  = (const float*)d_in[1];
    const float* conv1_w = (const float*)d_in[2];
    const float* conv1_b = (const float*)d_in[3];
    const float* conv2_w = (const float*)d_in[4];
    const float* conv2_b = (const float*)d_in[5];
    float* out = (float*)d_out;

    const int smem_bytes = (ND * XPAD + ND * NKS * NOUT + NOUT * WETP
                            + NOUT * HSP + 2 * NOUT) * sizeof(float);
    cudaFuncSetAttribute(main_kernel,
                         cudaFuncAttributeMaxDynamicSharedMemorySize, smem_bytes);

    prep_kernel<<<NG * NB, 256>>>(x, w_gate, conv2_w, conv2_b, out);
    main_kernel<<<dim3(NTILES, NB, NG), 256, smem_bytes>>>(x, conv1_w, conv1_b, out);
}

// round 9
// speedup vs baseline: 1.4197x; 1.0819x over previous
#include <cuda_runtime.h>
#include <math.h>

#define NG   8
#define ND   16
#define NL   1024
#define NB   16
#define NE   8
#define NOUT 64
#define NKS  3
#define NK   4
#define NLP  1022
#define TILE 128
#define NTILES 8
#define XPAD 132
#define HSP  136           // h smem row stride: 136%32=8 -> conflict-free frags

typedef unsigned long long u64;
typedef unsigned int u32;

// Scratch (static device globals — no allocation)
__device__ float g_gates[NG*NB*NE];
__device__ float g_beff[NG*NB*NOUT];
// W_eff in mma-fragment order: [blk][mt(4)][kt(8)][lane(32)] x float4(a0..a3)
__device__ float g_wfrag[NG*NB*4*8*32*4];

__device__ __forceinline__ float tanh_fast(float x) {
    float r;
    asm("tanh.approx.f32 %0, %1;" : "=f"(r) : "f"(x));
    return r;
}
__device__ __forceinline__ float round_tf32(float x) {
    u32 r;
    asm("cvt.rna.tf32.f32 %0, %1;" : "=r"(r) : "f"(x));
    return __uint_as_float(r);
}
__device__ __forceinline__ void ffma2(u64& d, u64 a, u64 b) {
    asm("fma.rn.f32x2 %0, %1, %2, %0;" : "+l"(d) : "l"(a), "l"(b));
}
__device__ __forceinline__ u64 pack_dup(float x) {
    u64 r; asm("mov.b64 %0, {%1, %1};" : "=l"(r) : "f"(x)); return r;
}
__device__ __forceinline__ float2 unpack2(u64 v) {
    float2 f; asm("mov.b64 {%0, %1}, %2;" : "=f"(f.x), "=f"(f.y) : "l"(v)); return f;
}
__device__ __forceinline__ void mma_tf32(float& c0, float& c1, float& c2, float& c3,
                                         u32 a0, u32 a1, u32 a2, u32 a3,
                                         u32 b0, u32 b1) {
    asm("mma.sync.aligned.m16n8k8.row.col.f32.tf32.tf32.f32 "
        "{%0,%1,%2,%3}, {%4,%5,%6,%7}, {%8,%9}, {%0,%1,%2,%3};"
        : "+f"(c0), "+f"(c1), "+f"(c2), "+f"(c3)
        : "r"(a0), "r"(a1), "r"(a2), "r"(a3), "r"(b0), "r"(b1));
}

__device__ __forceinline__ float cv_sq(const float* v) {
    float m = 0.f;
    #pragma unroll
    for (int i = 0; i < NE; i++) m += v[i];
    m *= (1.f / NE);
    float var = 0.f;
    #pragma unroll
    for (int i = 0; i < NE; i++) { float d = v[i] - m; var += d * d; }
    var *= (1.f / (NE - 1));
    return var / (m * m + 1e-10f);
}

// ---------------------------------------------------------------------------
// Kernel A: gates + W_eff fold -> fragment layout. One block per (g,b).
// ---------------------------------------------------------------------------
__global__ __launch_bounds__(256)
void prep_kernel(const float* __restrict__ x,
                 const float* __restrict__ w_gate,
                 const float* __restrict__ w2,
                 const float* __restrict__ b2,
                 float* __restrict__ out) {
    const int blk = blockIdx.x;   // g*NB + b
    const int g = blk >> 4;
    const int b = blk & 15;
    const int t = threadIdx.x;
    const int c = t & 31;
    const int r = t >> 5;

    __shared__ float gsm[NE];
    __shared__ float wef_s[NOUT * 65];   // [o][k] padded -> conflict-free frag gather

    // ---- warp 0: gates ----
    if (r == 0) {
        float plog[NE];
        #pragma unroll
        for (int e = 0; e < NE; e++) plog[e] = 0.f;
        #pragma unroll
        for (int i = c; i < ND * 5; i += 32) {
            int d = i / 5, j = i % 5;
            float xv = x[(size_t)b * (NG * ND * NL) + (size_t)(g * ND + d) * NL + (NL - 6 + j)];
            const float4* w4 = (const float4*)(w_gate + ((size_t)g * ND * 5 + i) * NE);
            float4 wa = w4[0], wb = w4[1];
            plog[0] += xv * wa.x; plog[1] += xv * wa.y;
            plog[2] += xv * wa.z; plog[3] += xv * wa.w;
            plog[4] += xv * wb.x; plog[5] += xv * wb.y;
            plog[6] += xv * wb.z; plog[7] += xv * wb.w;
        }
        #pragma unroll
        for (int off = 16; off >= 1; off >>= 1)
            #pragma unroll
            for (int e = 0; e < NE; e++)
                plog[e] += __shfl_xor_sync(0xffffffffu, plog[e], off);

        if (c == 0) {
            float m = plog[0];
            #pragma unroll
            for (int e = 1; e < NE; e++) m = fmaxf(m, plog[e]);
            float p[NE]; float s = 0.f;
            #pragma unroll
            for (int e = 0; e < NE; e++) { p[e] = __expf(plog[e] - m); s += p[e]; }
            float inv = 1.f / s;
            #pragma unroll
            for (int e = 0; e < NE; e++) p[e] *= inv;

            float q[NE];
            #pragma unroll
            for (int e = 0; e < NE; e++) q[e] = p[e];
            float tv[NK]; int ti[NK];
            #pragma unroll
            for (int k = 0; k < NK; k++) {
                float best = -1e30f; int bi = 0;
                #pragma unroll
                for (int e = 0; e < NE; e++)
                    if (q[e] > best) { best = q[e]; bi = e; }
                tv[k] = best; ti[k] = bi; q[bi] = -1e30f;
            }
            float dsum = tv[0] + tv[1] + tv[2] + tv[3] + 1e-6f;
            float gates[NE];
            #pragma unroll
            for (int e = 0; e < NE; e++) gates[e] = 0.f;
            #pragma unroll
            for (int k = 0; k < NK; k++) gates[ti[k]] = tv[k] / dsum;

            const size_t combine_sz = (size_t)NB * NG * NOUT * NLP;
            #pragma unroll
            for (int e = 0; e < NE; e++) {
                gsm[e] = gates[e];
                g_gates[blk * NE + e] = gates[e];
                out[combine_sz + 1 + (size_t)(b * NE + e) * NG + g] = gates[e];
            }
        }
    }
    __syncthreads();

    float gv[NE];
    #pragma unroll
    for (int e = 0; e < NE; e++) gv[e] = gsm[e];

    // fold (coalesced reads): wef_s[o][k] = tf32( sum_e gv[e] * w2[g][o*E+e][k] )
    const float* w2g = w2 + (size_t)g * NOUT * NE * NOUT;
    #pragma unroll
    for (int it = 0; it < (NOUT * NOUT) / 256; it++) {
        int idx = t + it * 256;
        int o = idx >> 6, k = idx & 63;
        const float* wrow = w2g + (size_t)o * NE * NOUT + k;
        float acc = 0.f;
        #pragma unroll
        for (int e = 0; e < NE; e++) acc += gv[e] * wrow[e * NOUT];
        wef_s[o * 65 + k] = round_tf32(acc);
    }
    if (t < NOUT) {
        const float* brow = b2 + (size_t)g * NOUT * NE + t * NE;
        float acc = 0.f;
        #pragma unroll
        for (int e = 0; e < NE; e++) acc += gv[e] * brow[e];
        g_beff[blk * NOUT + t] = acc;
    }
    __syncthreads();

    // emit fragment layout (coalesced float4 writes):
    // slot idx = mt*256 + kt*32 + lane ; val = (a0,a1,a2,a3) for that lane/warp
    float4* wfr = (float4*)g_wfrag + (size_t)blk * 1024;
    #pragma unroll
    for (int it = 0; it < 4; it++) {
        int idx = t + it * 256;
        int lane = idx & 31, kt = (idx >> 5) & 7, mt = idx >> 8;
        int gid = lane >> 2, tg = lane & 3;
        int k0 = kt * 8;
        float4 v;
        v.x = wef_s[(mt * 16 + gid)     * 65 + k0 + tg];
        v.y = wef_s[(mt * 16 + gid + 8) * 65 + k0 + tg];
        v.z = wef_s[(mt * 16 + gid)     * 65 + k0 + tg + 4];
        v.w = wef_s[(mt * 16 + gid + 8) * 65 + k0 + tg + 4];
        wfr[idx] = v;
    }
}

// ---------------------------------------------------------------------------
// Main kernel: conv1 (FFMA2) + tanh + tf32-MMA GEMM (A-frags via LDG.128).
// grid (NTILES, NB, NG), 256 threads, 4 blocks/SM.
// ---------------------------------------------------------------------------
__global__ __launch_bounds__(256, 4)
void main_kernel(const float* __restrict__ x,
                 const float* __restrict__ w1,
                 const float* __restrict__ b1,
                 float* __restrict__ out) {
    const int tile = blockIdx.x;
    const int b    = blockIdx.y;
    const int g    = blockIdx.z;
    const int l0g  = tile * TILE;
    const int tlen = min(TILE, NLP - l0g);
    const int blk  = g * NB + b;

    extern __shared__ float smem[];
    float* xs  = smem;                         // ND * XPAD     = 2112
    float* w1t = xs  + ND * XPAD;              // [d*3+k][o]    = 3072
    float* hs  = w1t + ND * NKS * NOUT;        // [k][l] pad136 = 8704 (tf32)
    float* b1s = hs  + NOUT * HSP;             // 64

    const int t = threadIdx.x;
    const int c = t & 31;          // lane
    const int r = t >> 5;          // warp id
    const int ob = r * 8;          // phase-2: 8 contiguous output channels
    const int l0 = c * 4;          // phase-2: 4 columns

    // ---- cooperative loads ----
    const float* xb = x + (size_t)b * (NG * ND * NL) + (size_t)g * ND * NL + l0g;
    const int ncols = min(TILE + 2, NL - l0g);
    for (int idx = t; idx < ND * XPAD; idx += 256) {
        int d = idx / XPAD, cc = idx % XPAD;
        xs[idx] = (cc < ncols) ? xb[(size_t)d * NL + cc] : 0.f;
    }
    const float* w1g = w1 + (size_t)g * NOUT * ND * NKS;
    for (int idx = t; idx < NOUT * ND * NKS; idx += 256) {
        int o = idx / (ND * NKS), dk = idx % (ND * NKS);
        w1t[dk * NOUT + o] = w1g[idx];
    }
    if (t < NOUT) b1s[t] = b1[g * NOUT + t];
    __syncthreads();

    // ---- phase 2: h = tanh(conv1(x)) in fp32 (FFMA2), tf32-rounded store ----
    {
        u64 acc2[4][4];
        #pragma unroll
        for (int i2 = 0; i2 < 4; i2++) {
            u64 bv = *(const u64*)&b1s[ob + 2 * i2];
            #pragma unroll
            for (int j = 0; j < 4; j++) acc2[i2][j] = bv;
        }
        #pragma unroll
        for (int d = 0; d < ND; d++) {
            const float4 xa = *(const float4*)&xs[d * XPAD + l0];
            const float4 xc = *(const float4*)&xs[d * XPAD + l0 + 4];
            u64 xd[6];
            xd[0] = pack_dup(xa.x); xd[1] = pack_dup(xa.y);
            xd[2] = pack_dup(xa.z); xd[3] = pack_dup(xa.w);
            xd[4] = pack_dup(xc.x); xd[5] = pack_dup(xc.y);
            #pragma unroll
            for (int k = 0; k < NKS; k++) {
                const ulonglong2 wp0 = *(const ulonglong2*)&w1t[(d * NKS + k) * NOUT + ob];
                const ulonglong2 wp1 = *(const ulonglong2*)&w1t[(d * NKS + k) * NOUT + ob + 4];
                const u64 wp[4] = {wp0.x, wp0.y, wp1.x, wp1.y};
                #pragma unroll
                for (int i2 = 0; i2 < 4; i2++) {
                    ffma2(acc2[i2][0], wp[i2], xd[k + 0]);
                    ffma2(acc2[i2][1], wp[i2], xd[k + 1]);
                    ffma2(acc2[i2][2], wp[i2], xd[k + 2]);
                    ffma2(acc2[i2][3], wp[i2], xd[k + 3]);
                }
            }
        }
        #pragma unroll
        for (int i2 = 0; i2 < 4; i2++) {
            float2 v0 = unpack2(acc2[i2][0]);
            float2 v1 = unpack2(acc2[i2][1]);
            float2 v2 = unpack2(acc2[i2][2]);
            float2 v3 = unpack2(acc2[i2][3]);
            *(float4*)&hs[(ob + 2 * i2) * HSP + l0] =
                make_float4(round_tf32(tanh_fast(v0.x)), round_tf32(tanh_fast(v1.x)),
                            round_tf32(tanh_fast(v2.x)), round_tf32(tanh_fast(v3.x)));
            *(float4*)&hs[(ob + 2 * i2 + 1) * HSP + l0] =
                make_float4(round_tf32(tanh_fast(v0.y)), round_tf32(tanh_fast(v1.y)),
                            round_tf32(tanh_fast(v2.y)), round_tf32(tanh_fast(v3.y)));
        }
    }
    __syncthreads();

    // ---- phase 3: out = W_eff @ h + b_eff via tf32 mma; A-frags from gmem ----
    {
        const int mt = r & 3;
        const int nh = r >> 2;
        const int gid = c >> 2;
        const int tg  = c & 3;
        const int orow0 = mt * 16 + gid;

        float cacc[8][4];
        const float bv0 = g_beff[blk * NOUT + orow0];
        const float bv1 = g_beff[blk * NOUT + orow0 + 8];
        #pragma unroll
        for (int nt = 0; nt < 8; nt++) {
            cacc[nt][0] = bv0; cacc[nt][1] = bv0;
            cacc[nt][2] = bv1; cacc[nt][3] = bv1;
        }
        const float4* wfr = (const float4*)g_wfrag + (size_t)blk * 1024 + mt * 256 + c;
        const u32* hsu = (const u32*)hs;

        float4 af = wfr[0];
        #pragma unroll
        for (int kt = 0; kt < 8; kt++) {
            const float4 nx = (kt < 7) ? wfr[(kt + 1) * 32] : af;
            const int k0 = kt * 8;
            const u32 a0 = __float_as_uint(af.x);
            const u32 a1 = __float_as_uint(af.y);
            const u32 a2 = __float_as_uint(af.z);
            const u32 a3 = __float_as_uint(af.w);
            #pragma unroll
            for (int nt = 0; nt < 8; nt++) {
                const int ncol = nh * 64 + nt * 8 + gid;
                const u32 b0 = hsu[(k0 + tg) * HSP + ncol];
                const u32 b1v = hsu[(k0 + tg + 4) * HSP + ncol];
                mma_tf32(cacc[nt][0], cacc[nt][1], cacc[nt][2], cacc[nt][3],
                         a0, a1, a2, a3, b0, b1v);
            }
            af = nx;
        }
        #pragma unroll
        for (int nt = 0; nt < 8; nt++) {
            const int colt = nh * 64 + nt * 8 + tg * 2;
            float* row0 = out + ((size_t)(b * NG + g) * NOUT + orow0) * NLP + l0g + colt;
            float* row1 = out + ((size_t)(b * NG + g) * NOUT + orow0 + 8) * NLP + l0g + colt;
            if (colt + 1 < tlen) {
                *(float2*)row0 = make_float2(cacc[nt][0], cacc[nt][1]);
                *(float2*)row1 = make_float2(cacc[nt][2], cacc[nt][3]);
            } else if (colt < tlen) {
                row0[0] = cacc[nt][0];
                row1[0] = cacc[nt][2];
            }
        }
    }

    // ---- loss tail: block (0,0,0) only; g_gates visible from prep_kernel ----
    if (tile == 0 && b == 0 && g == 0) {
        __syncthreads();
        float* s_imp = smem;              // reuse smem: [NG][NE]
        float* s_ld  = smem + NG * NE;
        float* lsum  = smem + 2 * NG * NE;
        if (t < NG * NE) {
            const int gg = t >> 3, e = t & 7;
            float imp = 0.f, ld = 0.f;
            #pragma unroll
            for (int bb = 0; bb < NB; bb++) {
                float v = g_gates[((gg * NB + bb) * NE) + e];
                imp += v;
                ld  += (v > 0.f) ? 1.f : 0.f;
            }
            s_imp[gg * NE + e] = imp;
            s_ld[gg * NE + e]  = ld;
        }
        __syncthreads();
        if (t < NG) lsum[t] = cv_sq(&s_imp[t * NE]) + cv_sq(&s_ld[t * NE]);
        __syncthreads();
        if (t == 0) {
            float total = 0.f;
            #pragma unroll
            for (int i = 0; i < NG; i++) total += lsum[i];
            out[(size_t)NB * NG * NOUT * NLP] = 0.01f * total;
        }
    }
}

// ---------------------------------------------------------------------------
extern "C" void kernel_launch(void* const* d_in, const int* in_sizes, int n_in,
                              void* d_out, int out_size) {
    const float* x       = (const float*)d_in[0];
    const float* w_gate  = (const float*)d_in[1];
    const float* conv1_w = (const float*)d_in[2];
    const float* conv1_b = (const float*)d_in[3];
    const float* conv2_w = (const float*)d_in[4];
    const float* conv2_b = (const float*)d_in[5];
    float* out = (float*)d_out;

    const int smem_bytes = (ND * XPAD + ND * NKS * NOUT
                            + NOUT * HSP + NOUT) * sizeof(float);
    cudaFuncSetAttribute(main_kernel,
                         cudaFuncAttributeMaxDynamicSharedMemorySize, smem_bytes);

    prep_kernel<<<NG * NB, 256>>>(x, w_gate, conv2_w, conv2_b, out);
    main_kernel<<<dim3(NTILES, NB, NG), 256, smem_bytes>>>(x, conv1_w, conv1_b, out);
}

// round 10
// speedup vs baseline: 1.5231x; 1.0728x over previous
#include <cuda_runtime.h>
#include <math.h>

#define NG   8
#define ND   16
#define NL   1024
#define NB   16
#define NE   8
#define NOUT 64
#define NKS  3
#define NK   4
#define NLP  1022
#define TILE 128
#define NTILES 8
#define XPAD 132
#define W1TP 68            // w1t row stride: 68%32=4 -> 4-way (not 32-way) STS
#define HSP  136           // h smem row stride: 136%32=8 -> conflict-free frags

typedef unsigned long long u64;
typedef unsigned int u32;

// Scratch (static device globals — no allocation)
__device__ float g_gates[NG*NB*NE];
__device__ float g_beff[NG*NB*NOUT];
// W_eff in mma-fragment order: [blk][mt(4)][kt(8)][lane(32)] x float4(a0..a3)
__device__ float g_wfrag[NG*NB*4*8*32*4];

__device__ __forceinline__ float tanh_fast(float x) {
    float r;
    asm("tanh.approx.f32 %0, %1;" : "=f"(r) : "f"(x));
    return r;
}
__device__ __forceinline__ float round_tf32(float x) {
    u32 r;
    asm("cvt.rna.tf32.f32 %0, %1;" : "=r"(r) : "f"(x));
    return __uint_as_float(r);
}
__device__ __forceinline__ void ffma2(u64& d, u64 a, u64 b) {
    asm("fma.rn.f32x2 %0, %1, %2, %0;" : "+l"(d) : "l"(a), "l"(b));
}
__device__ __forceinline__ u64 pack_dup(float x) {
    u64 r; asm("mov.b64 %0, {%1, %1};" : "=l"(r) : "f"(x)); return r;
}
__device__ __forceinline__ float2 unpack2(u64 v) {
    float2 f; asm("mov.b64 {%0, %1}, %2;" : "=f"(f.x), "=f"(f.y) : "l"(v)); return f;
}
__device__ __forceinline__ void mma_tf32(float& c0, float& c1, float& c2, float& c3,
                                         u32 a0, u32 a1, u32 a2, u32 a3,
                                         u32 b0, u32 b1) {
    asm("mma.sync.aligned.m16n8k8.row.col.f32.tf32.tf32.f32 "
        "{%0,%1,%2,%3}, {%4,%5,%6,%7}, {%8,%9}, {%0,%1,%2,%3};"
        : "+f"(c0), "+f"(c1), "+f"(c2), "+f"(c3)
        : "r"(a0), "r"(a1), "r"(a2), "r"(a3), "r"(b0), "r"(b1));
}

__device__ __forceinline__ float cv_sq(const float* v) {
    float m = 0.f;
    #pragma unroll
    for (int i = 0; i < NE; i++) m += v[i];
    m *= (1.f / NE);
    float var = 0.f;
    #pragma unroll
    for (int i = 0; i < NE; i++) { float d = v[i] - m; var += d * d; }
    var *= (1.f / (NE - 1));
    return var / (m * m + 1e-10f);
}

// ---------------------------------------------------------------------------
// Kernel A: gates + W_eff fold -> fragment layout. One block per (g,b).
// ---------------------------------------------------------------------------
__global__ __launch_bounds__(256)
void prep_kernel(const float* __restrict__ x,
                 const float* __restrict__ w_gate,
                 const float* __restrict__ w2,
                 const float* __restrict__ b2,
                 float* __restrict__ out) {
    const int blk = blockIdx.x;   // g*NB + b
    const int g = blk >> 4;
    const int b = blk & 15;
    const int t = threadIdx.x;
    const int c = t & 31;
    const int r = t >> 5;

    __shared__ float gsm[NE];
    __shared__ float wef_s[NOUT * 65];   // [o][k] padded -> conflict-free frag gather

    // ---- warp 0: gates ----
    if (r == 0) {
        float plog[NE];
        #pragma unroll
        for (int e = 0; e < NE; e++) plog[e] = 0.f;
        #pragma unroll
        for (int i = c; i < ND * 5; i += 32) {
            int d = i / 5, j = i % 5;
            float xv = x[(size_t)b * (NG * ND * NL) + (size_t)(g * ND + d) * NL + (NL - 6 + j)];
            const float4* w4 = (const float4*)(w_gate + ((size_t)g * ND * 5 + i) * NE);
            float4 wa = w4[0], wb = w4[1];
            plog[0] += xv * wa.x; plog[1] += xv * wa.y;
            plog[2] += xv * wa.z; plog[3] += xv * wa.w;
            plog[4] += xv * wb.x; plog[5] += xv * wb.y;
            plog[6] += xv * wb.z; plog[7] += xv * wb.w;
        }
        #pragma unroll
        for (int off = 16; off >= 1; off >>= 1)
            #pragma unroll
            for (int e = 0; e < NE; e++)
                plog[e] += __shfl_xor_sync(0xffffffffu, plog[e], off);

        if (c == 0) {
            float m = plog[0];
            #pragma unroll
            for (int e = 1; e < NE; e++) m = fmaxf(m, plog[e]);
            float p[NE]; float s = 0.f;
            #pragma unroll
            for (int e = 0; e < NE; e++) { p[e] = __expf(plog[e] - m); s += p[e]; }
            float inv = 1.f / s;
            #pragma unroll
            for (int e = 0; e < NE; e++) p[e] *= inv;

            float q[NE];
            #pragma unroll
            for (int e = 0; e < NE; e++) q[e] = p[e];
            float tv[NK]; int ti[NK];
            #pragma unroll
            for (int k = 0; k < NK; k++) {
                float best = -1e30f; int bi = 0;
                #pragma unroll
                for (int e = 0; e < NE; e++)
                    if (q[e] > best) { best = q[e]; bi = e; }
                tv[k] = best; ti[k] = bi; q[bi] = -1e30f;
            }
            float dsum = tv[0] + tv[1] + tv[2] + tv[3] + 1e-6f;
            float gates[NE];
            #pragma unroll
            for (int e = 0; e < NE; e++) gates[e] = 0.f;
            #pragma unroll
            for (int k = 0; k < NK; k++) gates[ti[k]] = tv[k] / dsum;

            const size_t combine_sz = (size_t)NB * NG * NOUT * NLP;
            #pragma unroll
            for (int e = 0; e < NE; e++) {
                gsm[e] = gates[e];
                g_gates[blk * NE + e] = gates[e];
                out[combine_sz + 1 + (size_t)(b * NE + e) * NG + g] = gates[e];
            }
        }
    }
    __syncthreads();

    float gv[NE];
    #pragma unroll
    for (int e = 0; e < NE; e++) gv[e] = gsm[e];

    // fold (coalesced reads): wef_s[o][k] = tf32( sum_e gv[e] * w2[g][o*E+e][k] )
    const float* w2g = w2 + (size_t)g * NOUT * NE * NOUT;
    #pragma unroll
    for (int it = 0; it < (NOUT * NOUT) / 256; it++) {
        int idx = t + it * 256;
        int o = idx >> 6, k = idx & 63;
        const float* wrow = w2g + (size_t)o * NE * NOUT + k;
        float acc = 0.f;
        #pragma unroll
        for (int e = 0; e < NE; e++) acc += gv[e] * wrow[e * NOUT];
        wef_s[o * 65 + k] = round_tf32(acc);
    }
    if (t < NOUT) {
        const float* brow = b2 + (size_t)g * NOUT * NE + t * NE;
        float acc = 0.f;
        #pragma unroll
        for (int e = 0; e < NE; e++) acc += gv[e] * brow[e];
        g_beff[blk * NOUT + t] = acc;
    }
    __syncthreads();

    // emit fragment layout (coalesced float4 writes):
    // slot idx = mt*256 + kt*32 + lane ; val = (a0,a1,a2,a3) for that lane/warp
    float4* wfr = (float4*)g_wfrag + (size_t)blk * 1024;
    #pragma unroll
    for (int it = 0; it < 4; it++) {
        int idx = t + it * 256;
        int lane = idx & 31, kt = (idx >> 5) & 7, mt = idx >> 8;
        int gid = lane >> 2, tg = lane & 3;
        int k0 = kt * 8;
        float4 v;
        v.x = wef_s[(mt * 16 + gid)     * 65 + k0 + tg];
        v.y = wef_s[(mt * 16 + gid + 8) * 65 + k0 + tg];
        v.z = wef_s[(mt * 16 + gid)     * 65 + k0 + tg + 4];
        v.w = wef_s[(mt * 16 + gid + 8) * 65 + k0 + tg + 4];
        wfr[idx] = v;
    }
}

// ---------------------------------------------------------------------------
// Main kernel: conv1 (FFMA2) + tanh + tf32-MMA GEMM (A-frags via LDG.128).
// grid (NTILES, NB, NG), 256 threads, 4 blocks/SM.
// ---------------------------------------------------------------------------
__global__ __launch_bounds__(256, 4)
void main_kernel(const float* __restrict__ x,
                 const float* __restrict__ w1,
                 const float* __restrict__ b1,
                 float* __restrict__ out) {
    const int tile = blockIdx.x;
    const int b    = blockIdx.y;
    const int g    = blockIdx.z;
    const int l0g  = tile * TILE;
    const int tlen = min(TILE, NLP - l0g);
    const int blk  = g * NB + b;

    extern __shared__ float smem[];
    float* xs  = smem;                         // ND * XPAD     = 2112
    float* w1t = xs  + ND * XPAD;              // [d*3+k][o] pad 68 = 3264
    float* hs  = w1t + ND * NKS * W1TP;        // [k][l] pad136 = 8704 (tf32)
    float* b1s = hs  + NOUT * HSP;             // 64

    const int t = threadIdx.x;
    const int c = t & 31;          // lane
    const int r = t >> 5;          // warp id
    const int ob = r * 8;          // phase-2: 8 contiguous output channels
    const int l0 = c * 4;          // phase-2: 4 columns

    // ---- cooperative loads ----
    const float* xb = x + (size_t)b * (NG * ND * NL) + (size_t)g * ND * NL + l0g;
    const int ncols = min(TILE + 2, NL - l0g);
    for (int idx = t; idx < ND * XPAD; idx += 256) {
        int d = idx / XPAD, cc = idx % XPAD;
        xs[idx] = (cc < ncols) ? xb[(size_t)d * NL + cc] : 0.f;
    }
    const float* w1g = w1 + (size_t)g * NOUT * ND * NKS;
    for (int idx = t; idx < NOUT * ND * NKS; idx += 256) {
        int o = idx / (ND * NKS), dk = idx % (ND * NKS);
        w1t[dk * W1TP + o] = w1g[idx];
    }
    if (t < NOUT) b1s[t] = b1[g * NOUT + t];
    __syncthreads();

    // ---- phase 2: h = tanh(conv1(x)) in fp32 (FFMA2), tf32-rounded store ----
    {
        u64 acc2[4][4];
        #pragma unroll
        for (int i2 = 0; i2 < 4; i2++) {
            u64 bv = *(const u64*)&b1s[ob + 2 * i2];
            #pragma unroll
            for (int j = 0; j < 4; j++) acc2[i2][j] = bv;
        }
        #pragma unroll
        for (int d = 0; d < ND; d++) {
            const float4 xa = *(const float4*)&xs[d * XPAD + l0];
            const float2 xc = *(const float2*)&xs[d * XPAD + l0 + 4];
            u64 xd[6];
            xd[0] = pack_dup(xa.x); xd[1] = pack_dup(xa.y);
            xd[2] = pack_dup(xa.z); xd[3] = pack_dup(xa.w);
            xd[4] = pack_dup(xc.x); xd[5] = pack_dup(xc.y);
            #pragma unroll
            for (int k = 0; k < NKS; k++) {
                const ulonglong2 wp0 = *(const ulonglong2*)&w1t[(d * NKS + k) * W1TP + ob];
                const ulonglong2 wp1 = *(const ulonglong2*)&w1t[(d * NKS + k) * W1TP + ob + 4];
                const u64 wp[4] = {wp0.x, wp0.y, wp1.x, wp1.y};
                #pragma unroll
                for (int i2 = 0; i2 < 4; i2++) {
                    ffma2(acc2[i2][0], wp[i2], xd[k + 0]);
                    ffma2(acc2[i2][1], wp[i2], xd[k + 1]);
                    ffma2(acc2[i2][2], wp[i2], xd[k + 2]);
                    ffma2(acc2[i2][3], wp[i2], xd[k + 3]);
                }
            }
        }
        #pragma unroll
        for (int i2 = 0; i2 < 4; i2++) {
            float2 v0 = unpack2(acc2[i2][0]);
            float2 v1 = unpack2(acc2[i2][1]);
            float2 v2 = unpack2(acc2[i2][2]);
            float2 v3 = unpack2(acc2[i2][3]);
            *(float4*)&hs[(ob + 2 * i2) * HSP + l0] =
                make_float4(round_tf32(tanh_fast(v0.x)), round_tf32(tanh_fast(v1.x)),
                            round_tf32(tanh_fast(v2.x)), round_tf32(tanh_fast(v3.x)));
            *(float4*)&hs[(ob + 2 * i2 + 1) * HSP + l0] =
                make_float4(round_tf32(tanh_fast(v0.y)), round_tf32(tanh_fast(v1.y)),
                            round_tf32(tanh_fast(v2.y)), round_tf32(tanh_fast(v3.y)));
        }
    }
    __syncthreads();

    // ---- phase 3: out = W_eff @ h + b_eff via tf32 mma; A-frags from gmem ----
    {
        const int mt = r & 3;
        const int nh = r >> 2;
        const int gid = c >> 2;
        const int tg  = c & 3;
        const int orow0 = mt * 16 + gid;

        float cacc[8][4];
        const float bv0 = g_beff[blk * NOUT + orow0];
        const float bv1 = g_beff[blk * NOUT + orow0 + 8];
        #pragma unroll
        for (int nt = 0; nt < 8; nt++) {
            cacc[nt][0] = bv0; cacc[nt][1] = bv0;
            cacc[nt][2] = bv1; cacc[nt][3] = bv1;
        }
        const float4* wfr = (const float4*)g_wfrag + (size_t)blk * 1024 + mt * 256 + c;
        const u32* hsu = (const u32*)hs;

        float4 af = wfr[0];
        #pragma unroll
        for (int kt = 0; kt < 8; kt++) {
            const float4 nx = (kt < 7) ? wfr[(kt + 1) * 32] : af;
            const int k0 = kt * 8;
            const u32 a0 = __float_as_uint(af.x);
            const u32 a1 = __float_as_uint(af.y);
            const u32 a2 = __float_as_uint(af.z);
            const u32 a3 = __float_as_uint(af.w);
            #pragma unroll
            for (int nt = 0; nt < 8; nt++) {
                const int ncol = nh * 64 + nt * 8 + gid;
                const u32 b0 = hsu[(k0 + tg) * HSP + ncol];
                const u32 b1v = hsu[(k0 + tg + 4) * HSP + ncol];
                mma_tf32(cacc[nt][0], cacc[nt][1], cacc[nt][2], cacc[nt][3],
                         a0, a1, a2, a3, b0, b1v);
            }
            af = nx;
        }
        #pragma unroll
        for (int nt = 0; nt < 8; nt++) {
            const int colt = nh * 64 + nt * 8 + tg * 2;
            float* row0 = out + ((size_t)(b * NG + g) * NOUT + orow0) * NLP + l0g + colt;
            float* row1 = out + ((size_t)(b * NG + g) * NOUT + orow0 + 8) * NLP + l0g + colt;
            if (colt + 1 < tlen) {
                *(float2*)row0 = make_float2(cacc[nt][0], cacc[nt][1]);
                *(float2*)row1 = make_float2(cacc[nt][2], cacc[nt][3]);
            } else if (colt < tlen) {
                row0[0] = cacc[nt][0];
                row1[0] = cacc[nt][2];
            }
        }
    }

    // ---- loss tail: block (0,0,0) only; g_gates visible from prep_kernel ----
    if (tile == 0 && b == 0 && g == 0) {
        __syncthreads();
        float* s_imp = smem;              // reuse smem: [NG][NE]
        float* s_ld  = smem + NG * NE;
        float* lsum  = smem + 2 * NG * NE;
        if (t < NG * NE) {
            const int gg = t >> 3, e = t & 7;
            float imp = 0.f, ld = 0.f;
            #pragma unroll
            for (int bb = 0; bb < NB; bb++) {
                float v = g_gates[((gg * NB + bb) * NE) + e];
                imp += v;
                ld  += (v > 0.f) ? 1.f : 0.f;
            }
            s_imp[gg * NE + e] = imp;
            s_ld[gg * NE + e]  = ld;
        }
        __syncthreads();
        if (t < NG) lsum[t] = cv_sq(&s_imp[t * NE]) + cv_sq(&s_ld[t * NE]);
        __syncthreads();
        if (t == 0) {
            float total = 0.f;
            #pragma unroll
            for (int i = 0; i < NG; i++) total += lsum[i];
            out[(size_t)NB * NG * NOUT * NLP] = 0.01f * total;
        }
    }
}

// ---------------------------------------------------------------------------
extern "C" void kernel_launch(void* const* d_in, const int* in_sizes, int n_in,
                              void* d_out, int out_size) {
    const float* x       = (const float*)d_in[0];
    const float* w_gate  = (const float*)d_in[1];
    const float* conv1_w = (const float*)d_in[2];
    const float* conv1_b = (const float*)d_in[3];
    const float* conv2_w = (const float*)d_in[4];
    const float* conv2_b = (const float*)d_in[5];
    float* out = (float*)d_out;

    const int smem_bytes = (ND * XPAD + ND * NKS * W1TP
                            + NOUT * HSP + NOUT) * sizeof(float);
    cudaFuncSetAttribute(main_kernel,
                         cudaFuncAttributeMaxDynamicSharedMemorySize, smem_bytes);

    prep_kernel<<<NG * NB, 256>>>(x, w_gate, conv2_w, conv2_b, out);
    main_kernel<<<dim3(NTILES, NB, NG), 256, smem_bytes>>>(x, conv1_w, conv1_b, out);
}

// round 11
// speedup vs baseline: 1.9394x; 1.2734x over previous
#include <cuda_runtime.h>
#include <math.h>

#define NG   8
#define ND   16
#define NL   1024
#define NB   16
#define NE   8
#define NOUT 64
#define NKS  3
#define NK   4
#define NLP  1022
#define TILE 128
#define NTILES 8
#define XPAD 136           // xs row stride: 136%32=8 -> conflict-free B-frags
#define HSP  136           // hs row stride

typedef unsigned long long u64;
typedef unsigned int u32;

// Scratch (static device globals — no allocation)
__device__ float g_gates[NG*NB*NE];
__device__ float g_beff[NG*NB*NOUT];
// W_eff in mma-fragment order: [blk][mt(4)][kt(8)][lane(32)] x float4
__device__ float g_wfrag[NG*NB*4*8*32*4];
// conv1 weights in mma-fragment order: [g][mt(4)][ks(3)][kt(2)][lane(32)] x float4
__device__ float g_w1frag[NG*4*3*2*32*4];

__device__ __forceinline__ float tanh_fast(float x) {
    float r;
    asm("tanh.approx.f32 %0, %1;" : "=f"(r) : "f"(x));
    return r;
}
__device__ __forceinline__ float round_tf32(float x) {
    u32 r;
    asm("cvt.rna.tf32.f32 %0, %1;" : "=r"(r) : "f"(x));
    return __uint_as_float(r);
}
__device__ __forceinline__ void mma_tf32(float& c0, float& c1, float& c2, float& c3,
                                         u32 a0, u32 a1, u32 a2, u32 a3,
                                         u32 b0, u32 b1) {
    asm("mma.sync.aligned.m16n8k8.row.col.f32.tf32.tf32.f32 "
        "{%0,%1,%2,%3}, {%4,%5,%6,%7}, {%8,%9}, {%0,%1,%2,%3};"
        : "+f"(c0), "+f"(c1), "+f"(c2), "+f"(c3)
        : "r"(a0), "r"(a1), "r"(a2), "r"(a3), "r"(b0), "r"(b1));
}

__device__ __forceinline__ float cv_sq(const float* v) {
    float m = 0.f;
    #pragma unroll
    for (int i = 0; i < NE; i++) m += v[i];
    m *= (1.f / NE);
    float var = 0.f;
    #pragma unroll
    for (int i = 0; i < NE; i++) { float d = v[i] - m; var += d * d; }
    var *= (1.f / (NE - 1));
    return var / (m * m + 1e-10f);
}

// ---------------------------------------------------------------------------
// Kernel A: gates + W_eff fold -> fragment layout; blocks with b==0 also
// emit conv1-weight fragments for their group. One block per (g,b).
// ---------------------------------------------------------------------------
__global__ __launch_bounds__(256)
void prep_kernel(const float* __restrict__ x,
                 const float* __restrict__ w_gate,
                 const float* __restrict__ w1,
                 const float* __restrict__ w2,
                 const float* __restrict__ b2,
                 float* __restrict__ out) {
    const int blk = blockIdx.x;   // g*NB + b
    const int g = blk >> 4;
    const int b = blk & 15;
    const int t = threadIdx.x;
    const int c = t & 31;
    const int r = t >> 5;

    __shared__ float gsm[NE];
    __shared__ float wef_s[NOUT * 65];

    // ---- warp 0: gates ----
    if (r == 0) {
        float plog[NE];
        #pragma unroll
        for (int e = 0; e < NE; e++) plog[e] = 0.f;
        #pragma unroll
        for (int i = c; i < ND * 5; i += 32) {
            int d = i / 5, j = i % 5;
            float xv = x[(size_t)b * (NG * ND * NL) + (size_t)(g * ND + d) * NL + (NL - 6 + j)];
            const float4* w4 = (const float4*)(w_gate + ((size_t)g * ND * 5 + i) * NE);
            float4 wa = w4[0], wb = w4[1];
            plog[0] += xv * wa.x; plog[1] += xv * wa.y;
            plog[2] += xv * wa.z; plog[3] += xv * wa.w;
            plog[4] += xv * wb.x; plog[5] += xv * wb.y;
            plog[6] += xv * wb.z; plog[7] += xv * wb.w;
        }
        #pragma unroll
        for (int off = 16; off >= 1; off >>= 1)
            #pragma unroll
            for (int e = 0; e < NE; e++)
                plog[e] += __shfl_xor_sync(0xffffffffu, plog[e], off);

        if (c == 0) {
            float m = plog[0];
            #pragma unroll
            for (int e = 1; e < NE; e++) m = fmaxf(m, plog[e]);
            float p[NE]; float s = 0.f;
            #pragma unroll
            for (int e = 0; e < NE; e++) { p[e] = __expf(plog[e] - m); s += p[e]; }
            float inv = 1.f / s;
            #pragma unroll
            for (int e = 0; e < NE; e++) p[e] *= inv;

            float q[NE];
            #pragma unroll
            for (int e = 0; e < NE; e++) q[e] = p[e];
            float tv[NK]; int ti[NK];
            #pragma unroll
            for (int k = 0; k < NK; k++) {
                float best = -1e30f; int bi = 0;
                #pragma unroll
                for (int e = 0; e < NE; e++)
                    if (q[e] > best) { best = q[e]; bi = e; }
                tv[k] = best; ti[k] = bi; q[bi] = -1e30f;
            }
            float dsum = tv[0] + tv[1] + tv[2] + tv[3] + 1e-6f;
            float gates[NE];
            #pragma unroll
            for (int e = 0; e < NE; e++) gates[e] = 0.f;
            #pragma unroll
            for (int k = 0; k < NK; k++) gates[ti[k]] = tv[k] / dsum;

            const size_t combine_sz = (size_t)NB * NG * NOUT * NLP;
            #pragma unroll
            for (int e = 0; e < NE; e++) {
                gsm[e] = gates[e];
                g_gates[blk * NE + e] = gates[e];
                out[combine_sz + 1 + (size_t)(b * NE + e) * NG + g] = gates[e];
            }
        }
    }

    // ---- b==0 blocks: conv1 weight fragments for group g ----
    if (b == 0) {
        const float* w1g = w1 + (size_t)g * NOUT * (ND * NKS);
        float4* wf1 = (float4*)g_w1frag + (size_t)g * 768;
        for (int idx = t; idx < 768; idx += 256) {
            const int lane = idx & 31;
            const int kt   = (idx >> 5) & 1;
            const int ks   = (idx >> 6) % 3;
            const int mt   = idx / 192;
            const int gid = lane >> 2, tg = lane & 3;
            const int row0 = mt * 16 + gid;
            const int colA = (kt * 8 + tg) * NKS + ks;
            const int colB = (kt * 8 + tg + 4) * NKS + ks;
            float4 v;
            v.x = round_tf32(w1g[row0 * (ND * NKS) + colA]);
            v.y = round_tf32(w1g[(row0 + 8) * (ND * NKS) + colA]);
            v.z = round_tf32(w1g[row0 * (ND * NKS) + colB]);
            v.w = round_tf32(w1g[(row0 + 8) * (ND * NKS) + colB]);
            wf1[idx] = v;
        }
    }
    __syncthreads();

    float gv[NE];
    #pragma unroll
    for (int e = 0; e < NE; e++) gv[e] = gsm[e];

    // fold: wef_s[o][k] = tf32( sum_e gv[e] * w2[g][o*E+e][k] )
    const float* w2g = w2 + (size_t)g * NOUT * NE * NOUT;
    #pragma unroll
    for (int it = 0; it < (NOUT * NOUT) / 256; it++) {
        int idx = t + it * 256;
        int o = idx >> 6, k = idx & 63;
        const float* wrow = w2g + (size_t)o * NE * NOUT + k;
        float acc = 0.f;
        #pragma unroll
        for (int e = 0; e < NE; e++) acc += gv[e] * wrow[e * NOUT];
        wef_s[o * 65 + k] = round_tf32(acc);
    }
    if (t < NOUT) {
        const float* brow = b2 + (size_t)g * NOUT * NE + t * NE;
        float acc = 0.f;
        #pragma unroll
        for (int e = 0; e < NE; e++) acc += gv[e] * brow[e];
        g_beff[blk * NOUT + t] = acc;
    }
    __syncthreads();

    // W_eff fragments: slot idx = mt*256 + kt*32 + lane
    float4* wfr = (float4*)g_wfrag + (size_t)blk * 1024;
    #pragma unroll
    for (int it = 0; it < 4; it++) {
        int idx = t + it * 256;
        int lane = idx & 31, kt = (idx >> 5) & 7, mt = idx >> 8;
        int gid = lane >> 2, tg = lane & 3;
        int k0 = kt * 8;
        float4 v;
        v.x = wef_s[(mt * 16 + gid)     * 65 + k0 + tg];
        v.y = wef_s[(mt * 16 + gid + 8) * 65 + k0 + tg];
        v.z = wef_s[(mt * 16 + gid)     * 65 + k0 + tg + 4];
        v.w = wef_s[(mt * 16 + gid + 8) * 65 + k0 + tg + 4];
        wfr[idx] = v;
    }
}

// ---------------------------------------------------------------------------
// Main kernel: both conv1 and GEMM on the tensor pipe. 2 tiles per block.
// grid (NTILES/2, NB, NG) = 512 blocks, 256 threads, 4 blocks/SM.
// ---------------------------------------------------------------------------
__global__ __launch_bounds__(256, 4)
void main_kernel(const float* __restrict__ x,
                 const float* __restrict__ b1,
                 float* __restrict__ out) {
    const int b   = blockIdx.y;
    const int g   = blockIdx.z;
    const int blk = g * NB + b;

    extern __shared__ float smem[];
    float* xs  = smem;                 // [d][l] 16*136 = 2176 (tf32)
    float* hs  = xs + ND * XPAD;       // [k][l] 64*136 = 8704 (tf32)
    float* b1s = hs + NOUT * HSP;      // 64

    const int t = threadIdx.x;
    const int c = t & 31;
    const int r = t >> 5;
    const int mt = r & 3;
    const int nh = r >> 2;
    const int gid = c >> 2;
    const int tg  = c & 3;
    const int orow0 = mt * 16 + gid;

    if (t < NOUT) b1s[t] = b1[g * NOUT + t];

    const float* xb0 = x + (size_t)b * (NG * ND * NL) + (size_t)g * ND * NL;
    const float4* wf1 = (const float4*)g_w1frag + (size_t)g * 768 + mt * 192 + c;
    const float4* wfr = (const float4*)g_wfrag + (size_t)blk * 1024 + mt * 256 + c;
    const float h_bv0 = b1[g * NOUT + orow0];        // (also via b1s after sync)
    const float e_bv0 = g_beff[blk * NOUT + orow0];
    const float e_bv1 = g_beff[blk * NOUT + orow0 + 8];

    #pragma unroll
    for (int it = 0; it < 2; it++) {
        const int tile = blockIdx.x * 2 + it;
        const int l0g  = tile * TILE;
        const int tlen = min(TILE, NLP - l0g);

        // ---- stage x tile (tf32-rounded, zero-padded) ----
        for (int idx = t; idx < ND * XPAD; idx += 256) {
            const int d = idx / XPAD, l = idx % XPAD;
            const int gx = l0g + l;
            xs[idx] = round_tf32((gx < NL) ? xb0[(size_t)d * NL + gx] : 0.f);
        }
        __syncthreads();   // xs ready; previous tile's phase-3 hs reads done

        // ---- phase 2: h = tanh(conv1(x)) via tf32 mma (3 shifted GEMMs) ----
        {
            float cacc[8][4];
            const float bv0 = b1s[orow0];
            const float bv1 = b1s[orow0 + 8];
            #pragma unroll
            for (int nt = 0; nt < 8; nt++) {
                cacc[nt][0] = bv0; cacc[nt][1] = bv0;
                cacc[nt][2] = bv1; cacc[nt][3] = bv1;
            }
            const u32* xsu = (const u32*)xs;
            #pragma unroll
            for (int ks = 0; ks < NKS; ks++) {
                #pragma unroll
                for (int kt = 0; kt < 2; kt++) {
                    const float4 af = wf1[ks * 64 + kt * 32];
                    const u32 a0 = __float_as_uint(af.x);
                    const u32 a1 = __float_as_uint(af.y);
                    const u32 a2 = __float_as_uint(af.z);
                    const u32 a3 = __float_as_uint(af.w);
                    const int d0 = kt * 8;
                    #pragma unroll
                    for (int nt = 0; nt < 8; nt++) {
                        const int ncol = nh * 64 + nt * 8 + gid + ks;
                        const u32 b0 = xsu[(d0 + tg) * XPAD + ncol];
                        const u32 b1v = xsu[(d0 + tg + 4) * XPAD + ncol];
                        mma_tf32(cacc[nt][0], cacc[nt][1], cacc[nt][2], cacc[nt][3],
                                 a0, a1, a2, a3, b0, b1v);
                    }
                }
            }
            #pragma unroll
            for (int nt = 0; nt < 8; nt++) {
                const int colt = nh * 64 + nt * 8 + tg * 2;
                *(float2*)&hs[orow0 * HSP + colt] =
                    make_float2(round_tf32(tanh_fast(cacc[nt][0])),
                                round_tf32(tanh_fast(cacc[nt][1])));
                *(float2*)&hs[(orow0 + 8) * HSP + colt] =
                    make_float2(round_tf32(tanh_fast(cacc[nt][2])),
                                round_tf32(tanh_fast(cacc[nt][3])));
            }
        }
        __syncthreads();

        // ---- phase 3: out = W_eff @ h + b_eff via tf32 mma ----
        {
            float cacc[8][4];
            #pragma unroll
            for (int nt = 0; nt < 8; nt++) {
                cacc[nt][0] = e_bv0; cacc[nt][1] = e_bv0;
                cacc[nt][2] = e_bv1; cacc[nt][3] = e_bv1;
            }
            const u32* hsu = (const u32*)hs;
            #pragma unroll
            for (int kt = 0; kt < 8; kt++) {
                const float4 af = wfr[kt * 32];
                const int k0 = kt * 8;
                const u32 a0 = __float_as_uint(af.x);
                const u32 a1 = __float_as_uint(af.y);
                const u32 a2 = __float_as_uint(af.z);
                const u32 a3 = __float_as_uint(af.w);
                #pragma unroll
                for (int nt = 0; nt < 8; nt++) {
                    const int ncol = nh * 64 + nt * 8 + gid;
                    const u32 b0 = hsu[(k0 + tg) * HSP + ncol];
                    const u32 b1v = hsu[(k0 + tg + 4) * HSP + ncol];
                    mma_tf32(cacc[nt][0], cacc[nt][1], cacc[nt][2], cacc[nt][3],
                             a0, a1, a2, a3, b0, b1v);
                }
            }
            #pragma unroll
            for (int nt = 0; nt < 8; nt++) {
                const int colt = nh * 64 + nt * 8 + tg * 2;
                float* row0 = out + ((size_t)(b * NG + g) * NOUT + orow0) * NLP + l0g + colt;
                float* row1 = out + ((size_t)(b * NG + g) * NOUT + orow0 + 8) * NLP + l0g + colt;
                if (colt + 1 < tlen) {
                    *(float2*)row0 = make_float2(cacc[nt][0], cacc[nt][1]);
                    *(float2*)row1 = make_float2(cacc[nt][2], cacc[nt][3]);
                } else if (colt < tlen) {
                    row0[0] = cacc[nt][0];
                    row1[0] = cacc[nt][2];
                }
            }
        }
    }
    (void)h_bv0;

    // ---- loss tail: block (0,0,0) ----
    if (blockIdx.x == 0 && b == 0 && g == 0) {
        __syncthreads();
        float* s_imp = smem;
        float* s_ld  = smem + NG * NE;
        float* lsum  = smem + 2 * NG * NE;
        if (t < NG * NE) {
            const int gg = t >> 3, e = t & 7;
            float imp = 0.f, ld = 0.f;
            #pragma unroll
            for (int bb = 0; bb < NB; bb++) {
                float v = g_gates[((gg * NB + bb) * NE) + e];
                imp += v;
                ld  += (v > 0.f) ? 1.f : 0.f;
            }
            s_imp[gg * NE + e] = imp;
            s_ld[gg * NE + e]  = ld;
        }
        __syncthreads();
        if (t < NG) lsum[t] = cv_sq(&s_imp[t * NE]) + cv_sq(&s_ld[t * NE]);
        __syncthreads();
        if (t == 0) {
            float total = 0.f;
            #pragma unroll
            for (int i = 0; i < NG; i++) total += lsum[i];
            out[(size_t)NB * NG * NOUT * NLP] = 0.01f * total;
        }
    }
}

// ---------------------------------------------------------------------------
extern "C" void kernel_launch(void* const* d_in, const int* in_sizes, int n_in,
                              void* d_out, int out_size) {
    const float* x       = (const float*)d_in[0];
    const float* w_gate  = (const float*)d_in[1];
    const float* conv1_w = (const float*)d_in[2];
    const float* conv1_b = (const float*)d_in[3];
    const float* conv2_w = (const float*)d_in[4];
    const float* conv2_b = (const float*)d_in[5];
    float* out = (float*)d_out;

    const int smem_bytes = (ND * XPAD + NOUT * HSP + NOUT) * sizeof(float);
    cudaFuncSetAttribute(main_kernel,
                         cudaFuncAttributeMaxDynamicSharedMemorySize, smem_bytes);

    prep_kernel<<<NG * NB, 256>>>(x, w_gate, conv1_w, conv2_w, conv2_b, out);
    main_kernel<<<dim3(NTILES / 2, NB, NG), 256, smem_bytes>>>(x, conv1_b, out);
}

// round 12
// speedup vs baseline: 2.0346x; 1.0491x over previous
#include <cuda_runtime.h>
#include <math.h>

#define NG   8
#define ND   16
#define NL   1024
#define NB   16
#define NE   8
#define NOUT 64
#define NKS  3
#define NK   4
#define NLP  1022
#define TILE 128
#define XPAD 136           // xs row stride (136%32=8 -> conflict-free B-frags)
#define HSP  72            // hs row stride for 64-col chunks (72%32=8)
#define WSP  65            // wef_s fold stride (overlaid on hs)

typedef unsigned int u32;

// Scratch (static device globals — no allocation)
__device__ float g_gates[NG*NB*NE];
__device__ unsigned g_counter;   // zero-init; reset by loss block each launch

__device__ __forceinline__ float tanh_fast(float x) {
    float r;
    asm("tanh.approx.f32 %0, %1;" : "=f"(r) : "f"(x));
    return r;
}
__device__ __forceinline__ float round_tf32(float x) {
    u32 r;
    asm("cvt.rna.tf32.f32 %0, %1;" : "=r"(r) : "f"(x));
    return __uint_as_float(r);
}
__device__ __forceinline__ u32 round_tf32_u(float x) {
    u32 r;
    asm("cvt.rna.tf32.f32 %0, %1;" : "=r"(r) : "f"(x));
    return r;
}
__device__ __forceinline__ void mma_tf32(float& c0, float& c1, float& c2, float& c3,
                                         u32 a0, u32 a1, u32 a2, u32 a3,
                                         u32 b0, u32 b1) {
    asm("mma.sync.aligned.m16n8k8.row.col.f32.tf32.tf32.f32 "
        "{%0,%1,%2,%3}, {%4,%5,%6,%7}, {%8,%9}, {%0,%1,%2,%3};"
        : "+f"(c0), "+f"(c1), "+f"(c2), "+f"(c3)
        : "r"(a0), "r"(a1), "r"(a2), "r"(a3), "r"(b0), "r"(b1));
}

__device__ __forceinline__ float cv_sq(const float* v) {
    float m = 0.f;
    #pragma unroll
    for (int i = 0; i < NE; i++) m += v[i];
    m *= (1.f / NE);
    float var = 0.f;
    #pragma unroll
    for (int i = 0; i < NE; i++) { float d = v[i] - m; var += d * d; }
    var *= (1.f / (NE - 1));
    return var / (m * m + 1e-10f);
}

// ---------------------------------------------------------------------------
// Fused kernel. grid (4, NB, NG) = 512 blocks, 256 threads, 44KB static smem.
// Each block: gates (warp0) + W_eff fold + 2 tiles x (conv1-mma + GEMM-mma)
// in 64-col chunks. Loss in block (0,0,0) after an atomic-counter rendezvous.
// ---------------------------------------------------------------------------
__global__ __launch_bounds__(256, 4)
void fused_kernel(const float* __restrict__ x,
                  const float* __restrict__ w_gate,
                  const float* __restrict__ w1,
                  const float* __restrict__ b1,
                  const float* __restrict__ w2,
                  const float* __restrict__ b2,
                  float* __restrict__ out) {
    const int bx = blockIdx.x;    // tile pair
    const int b  = blockIdx.y;
    const int g  = blockIdx.z;
    const int blk = g * NB + b;

    __shared__ float  xs[ND * XPAD];      // 2176 floats
    __shared__ float  hs[NOUT * HSP];     // 4608 floats (early: wef_s stride 65)
    __shared__ float4 frag[1024];         // W_eff A-fragments (16KB)
    __shared__ float  b1s[NOUT];
    __shared__ float  bes[NOUT];
    __shared__ float  gsm[NE];

    const int t = threadIdx.x;
    const int c = t & 31;
    const int r = t >> 5;
    const int mt = r & 3;
    const int nh = r >> 2;         // 0/1 -> 32-col half of each 64-col chunk
    const int gid = c >> 2;
    const int tg  = c & 3;
    const int orow0 = mt * 16 + gid;

    const float* xb0 = x + (size_t)b * (NG * ND * NL) + (size_t)g * ND * NL;

    // ==== step 1: warp 0 computes gates; warps 1-7 stage xs tile0 + b1s ====
    if (r == 0) {
        float plog[NE];
        #pragma unroll
        for (int e = 0; e < NE; e++) plog[e] = 0.f;
        #pragma unroll
        for (int i = c; i < ND * 5; i += 32) {
            int d = i / 5, j = i % 5;
            float xv = xb0[(size_t)d * NL + (NL - 6 + j)];
            const float4* w4 = (const float4*)(w_gate + ((size_t)g * ND * 5 + i) * NE);
            float4 wa = w4[0], wb = w4[1];
            plog[0] += xv * wa.x; plog[1] += xv * wa.y;
            plog[2] += xv * wa.z; plog[3] += xv * wa.w;
            plog[4] += xv * wb.x; plog[5] += xv * wb.y;
            plog[6] += xv * wb.z; plog[7] += xv * wb.w;
        }
        #pragma unroll
        for (int off = 16; off >= 1; off >>= 1)
            #pragma unroll
            for (int e = 0; e < NE; e++)
                plog[e] += __shfl_xor_sync(0xffffffffu, plog[e], off);

        if (c == 0) {
            float m = plog[0];
            #pragma unroll
            for (int e = 1; e < NE; e++) m = fmaxf(m, plog[e]);
            float p[NE]; float s = 0.f;
            #pragma unroll
            for (int e = 0; e < NE; e++) { p[e] = __expf(plog[e] - m); s += p[e]; }
            float inv = 1.f / s;
            #pragma unroll
            for (int e = 0; e < NE; e++) p[e] *= inv;

            float q[NE];
            #pragma unroll
            for (int e = 0; e < NE; e++) q[e] = p[e];
            float tv[NK]; int ti[NK];
            #pragma unroll
            for (int k = 0; k < NK; k++) {
                float best = -1e30f; int bi = 0;
                #pragma unroll
                for (int e = 0; e < NE; e++)
                    if (q[e] > best) { best = q[e]; bi = e; }
                tv[k] = best; ti[k] = bi; q[bi] = -1e30f;
            }
            float dsum = tv[0] + tv[1] + tv[2] + tv[3] + 1e-6f;
            float gates[NE];
            #pragma unroll
            for (int e = 0; e < NE; e++) gates[e] = 0.f;
            #pragma unroll
            for (int k = 0; k < NK; k++) gates[ti[k]] = tv[k] / dsum;

            #pragma unroll
            for (int e = 0; e < NE; e++) gsm[e] = gates[e];
            if (bx == 0) {
                const size_t combine_sz = (size_t)NB * NG * NOUT * NLP;
                #pragma unroll
                for (int e = 0; e < NE; e++) {
                    g_gates[blk * NE + e] = gates[e];
                    out[combine_sz + 1 + (size_t)(b * NE + e) * NG + g] = gates[e];
                }
                __threadfence();
                atomicAdd(&g_counter, 1u);
            }
        }
    } else {
        const int tt = t - 32;     // 0..223
        if (tt < NOUT) b1s[tt] = b1[g * NOUT + tt];
        const int l0g0 = bx * 2 * TILE;
        for (int idx = tt; idx < ND * XPAD; idx += 224) {
            const int d = idx / XPAD, l = idx % XPAD;
            const int gx = l0g0 + l;
            xs[idx] = round_tf32((gx < NL) ? xb0[(size_t)d * NL + gx] : 0.f);
        }
    }
    __syncthreads();   // gsm, xs(tile0), b1s ready

    // ==== step 2: gather w1 A-fragments (regs) + fold W_eff into hs area ====
    u32 wf[6][4];      // [ks*2+kt][a0..a3]
    {
        const float* w1g = w1 + (size_t)g * NOUT * (ND * NKS);
        #pragma unroll
        for (int ks = 0; ks < NKS; ks++)
            #pragma unroll
            for (int kt = 0; kt < 2; kt++) {
                const int colA = (kt * 8 + tg) * NKS + ks;
                const int colB = (kt * 8 + tg + 4) * NKS + ks;
                wf[ks * 2 + kt][0] = round_tf32_u(w1g[orow0 * 48 + colA]);
                wf[ks * 2 + kt][1] = round_tf32_u(w1g[(orow0 + 8) * 48 + colA]);
                wf[ks * 2 + kt][2] = round_tf32_u(w1g[orow0 * 48 + colB]);
                wf[ks * 2 + kt][3] = round_tf32_u(w1g[(orow0 + 8) * 48 + colB]);
            }
    }
    {
        float gv[NE];
        #pragma unroll
        for (int e = 0; e < NE; e++) gv[e] = gsm[e];
        const float* w2g = w2 + (size_t)g * NOUT * NE * NOUT;
        #pragma unroll
        for (int it = 0; it < (NOUT * NOUT) / 256; it++) {
            int idx = t + it * 256;
            int o = idx >> 6, k = idx & 63;
            const float* wrow = w2g + (size_t)o * NE * NOUT + k;
            float acc = 0.f;
            #pragma unroll
            for (int e = 0; e < NE; e++) acc += gv[e] * wrow[e * NOUT];
            hs[o * WSP + k] = round_tf32(acc);     // wef_s overlay
        }
        if (t < NOUT) {
            const float* brow = b2 + (size_t)g * NOUT * NE + t * NE;
            float acc = 0.f;
            #pragma unroll
            for (int e = 0; e < NE; e++) acc += gv[e] * brow[e];
            bes[t] = acc;
        }
    }
    __syncthreads();

    // ==== step 3: emit W_eff A-fragments into frag[] ====
    #pragma unroll
    for (int it = 0; it < 4; it++) {
        int idx = t + it * 256;
        int lane = idx & 31, kt = (idx >> 5) & 7, fmt = idx >> 8;
        int fgid = lane >> 2, ftg = lane & 3;
        int k0 = kt * 8;
        float4 v;
        v.x = hs[(fmt * 16 + fgid)     * WSP + k0 + ftg];
        v.y = hs[(fmt * 16 + fgid + 8) * WSP + k0 + ftg];
        v.z = hs[(fmt * 16 + fgid)     * WSP + k0 + ftg + 4];
        v.w = hs[(fmt * 16 + fgid + 8) * WSP + k0 + ftg + 4];
        frag[idx] = v;
    }
    __syncthreads();

    // ==== tiles ====
    const u32* xsu = (const u32*)xs;
    const u32* hsu = (const u32*)hs;

    #pragma unroll
    for (int it = 0; it < 2; it++) {
        const int tile = bx * 2 + it;
        const int l0g  = tile * TILE;
        const int tlen = min(TILE, NLP - l0g);

        #pragma unroll
        for (int ch = 0; ch < 2; ch++) {
            // ---- phase 2: h-chunk = tanh(conv1) via tf32 mma ----
            {
                float cacc[4][4];
                const float bv0 = b1s[orow0];
                const float bv1 = b1s[orow0 + 8];
                #pragma unroll
                for (int nt = 0; nt < 4; nt++) {
                    cacc[nt][0] = bv0; cacc[nt][1] = bv0;
                    cacc[nt][2] = bv1; cacc[nt][3] = bv1;
                }
                #pragma unroll
                for (int ks = 0; ks < NKS; ks++)
                    #pragma unroll
                    for (int kt = 0; kt < 2; kt++) {
                        const u32 a0 = wf[ks * 2 + kt][0];
                        const u32 a1 = wf[ks * 2 + kt][1];
                        const u32 a2 = wf[ks * 2 + kt][2];
                        const u32 a3 = wf[ks * 2 + kt][3];
                        const int d0 = kt * 8;
                        #pragma unroll
                        for (int nt = 0; nt < 4; nt++) {
                            const int ncol = ch * 64 + nh * 32 + nt * 8 + gid + ks;
                            const u32 b0 = xsu[(d0 + tg) * XPAD + ncol];
                            const u32 b1v = xsu[(d0 + tg + 4) * XPAD + ncol];
                            mma_tf32(cacc[nt][0], cacc[nt][1], cacc[nt][2], cacc[nt][3],
                                     a0, a1, a2, a3, b0, b1v);
                        }
                    }
                #pragma unroll
                for (int nt = 0; nt < 4; nt++) {
                    const int colt = nh * 32 + nt * 8 + tg * 2;
                    *(float2*)&hs[orow0 * HSP + colt] =
                        make_float2(round_tf32(tanh_fast(cacc[nt][0])),
                                    round_tf32(tanh_fast(cacc[nt][1])));
                    *(float2*)&hs[(orow0 + 8) * HSP + colt] =
                        make_float2(round_tf32(tanh_fast(cacc[nt][2])),
                                    round_tf32(tanh_fast(cacc[nt][3])));
                }
            }
            __syncthreads();

            // stage next tile's xs once this tile's phase 2 is fully done
            if (it == 0 && ch == 1) {
                const int l0g1 = (bx * 2 + 1) * TILE;
                for (int idx = t; idx < ND * XPAD; idx += 256) {
                    const int d = idx / XPAD, l = idx % XPAD;
                    const int gx = l0g1 + l;
                    xs[idx] = round_tf32((gx < NL) ? xb0[(size_t)d * NL + gx] : 0.f);
                }
            }

            // ---- phase 3: out-chunk = W_eff @ h + b_eff via tf32 mma ----
            {
                float cacc[4][4];
                const float bv0 = bes[orow0];
                const float bv1 = bes[orow0 + 8];
                #pragma unroll
                for (int nt = 0; nt < 4; nt++) {
                    cacc[nt][0] = bv0; cacc[nt][1] = bv0;
                    cacc[nt][2] = bv1; cacc[nt][3] = bv1;
                }
                #pragma unroll
                for (int kt = 0; kt < 8; kt++) {
                    const float4 af = frag[mt * 256 + kt * 32 + c];
                    const int k0 = kt * 8;
                    const u32 a0 = __float_as_uint(af.x);
                    const u32 a1 = __float_as_uint(af.y);
                    const u32 a2 = __float_as_uint(af.z);
                    const u32 a3 = __float_as_uint(af.w);
                    #pragma unroll
                    for (int nt = 0; nt < 4; nt++) {
                        const int ncol = nh * 32 + nt * 8 + gid;
                        const u32 b0 = hsu[(k0 + tg) * HSP + ncol];
                        const u32 b1v = hsu[(k0 + tg + 4) * HSP + ncol];
                        mma_tf32(cacc[nt][0], cacc[nt][1], cacc[nt][2], cacc[nt][3],
                                 a0, a1, a2, a3, b0, b1v);
                    }
                }
                #pragma unroll
                for (int nt = 0; nt < 4; nt++) {
                    const int colt = ch * 64 + nh * 32 + nt * 8 + tg * 2;
                    float* row0 = out + ((size_t)(b * NG + g) * NOUT + orow0) * NLP + l0g + colt;
                    float* row1 = out + ((size_t)(b * NG + g) * NOUT + orow0 + 8) * NLP + l0g + colt;
                    if (colt + 1 < tlen) {
                        *(float2*)row0 = make_float2(cacc[nt][0], cacc[nt][1]);
                        *(float2*)row1 = make_float2(cacc[nt][2], cacc[nt][3]);
                    } else if (colt < tlen) {
                        row0[0] = cacc[nt][0];
                        row1[0] = cacc[nt][2];
                    }
                }
            }
            __syncthreads();
        }
    }

    // ==== loss: block (0,0,0) waits for all 128 gate writers, then computes ====
    if (bx == 0 && b == 0 && g == 0) {
        if (t == 0) {
            while (atomicAdd(&g_counter, 0u) < (unsigned)(NG * NB)) { }
            __threadfence();
        }
        __syncthreads();
        float* s_imp = xs;               // reuse xs region
        float* s_ld  = xs + NG * NE;
        float* lsum  = xs + 2 * NG * NE;
        if (t < NG * NE) {
            const int gg = t >> 3, e = t & 7;
            float imp = 0.f, ld = 0.f;
            #pragma unroll
            for (int bb = 0; bb < NB; bb++) {
                float v = g_gates[((gg * NB + bb) * NE) + e];
                imp += v;
                ld  += (v > 0.f) ? 1.f : 0.f;
            }
            s_imp[gg * NE + e] = imp;
            s_ld[gg * NE + e]  = ld;
        }
        __syncthreads();
        if (t < NG) lsum[t] = cv_sq(&s_imp[t * NE]) + cv_sq(&s_ld[t * NE]);
        __syncthreads();
        if (t == 0) {
            float total = 0.f;
            #pragma unroll
            for (int i = 0; i < NG; i++) total += lsum[i];
            out[(size_t)NB * NG * NOUT * NLP] = 0.01f * total;
            __threadfence();
            atomicExch(&g_counter, 0u);   // reset for next graph replay
        }
    }
}

// ---------------------------------------------------------------------------
extern "C" void kernel_launch(void* const* d_in, const int* in_sizes, int n_in,
                              void* d_out, int out_size) {
    const float* x       = (const float*)d_in[0];
    const float* w_gate  = (const float*)d_in[1];
    const float* conv1_w = (const float*)d_in[2];
    const float* conv1_b = (const float*)d_in[3];
    const float* conv2_w = (const float*)d_in[4];
    const float* conv2_b = (const float*)d_in[5];
    float* out = (float*)d_out;

    fused_kernel<<<dim3(4, NB, NG), 256>>>(
        x, w_gate, conv1_w, conv1_b, conv2_w, conv2_b, out);
}